// round 14
// baseline (speedup 1.0000x reference)
#include <cuda_runtime.h>
#include <math.h>

#define NL 4
#define NB 16
#define NN 256
#define NC 16
#define NHID 64
#define INV256F (1.0f/256.0f)
#define INVNORM 0.06454972243679028f   /* 1/sqrt(240) */
#define OW_STRIDE 16842752             /* per-layer stride in d_out (ow + ob) */
#define OB_OFF    16777216             /* offset of ob within a layer chunk */

// ---------------- scratch (device globals; no allocs) ----------------
__device__ float g_terms[100*256];          // 100 siren points x (16c x 16d)
__device__ float g_rsums[NL*NB*NN*NC];      // mean over j  -> [l][b][k][c]
__device__ float g_csums[NL*NB*NN*NC];      // mean over k  -> [l][b][j][c]
__device__ float g_rpart[4*NL*NB*NN*NC];    // 4 j-quarter partial sums over j
__device__ float g_cpart[2*NL*NB*NN*NC];    // 2 k-half partial sums over k
__device__ float g_allsums[NB*NC*NL];       // [b][c][l]
__device__ float g_sumsb[NB*NC*NL];         // [b][c][l]
__device__ float g_basew[NL*NB*NC];         // [l][b][d]
__device__ float g_rowterm[NL*NB*NN*NC];    // [l][b][k][d]

// g_terms point layout:
// global: t*16 + a*4 + b   (t=0..3)
// diag:   64 + t*4 + i     (t=0..5)
// p1:     88 + t*3 + i     (t=0..1, i=0..2)
// m1:     94 + t*3 + i

__device__ __forceinline__ float f_li(int i){ return -1.0f + (2.0f/3.0f)*i; }
__device__ __forceinline__ float f_ti(int m){ return -1.0f + (2.0f/13.0f)*m; }

__device__ __forceinline__ unsigned long long pack2(float lo, float hi){
    unsigned long long r;
    asm("mov.b64 %0, {%1, %2};" : "=l"(r) : "f"(lo), "f"(hi));
    return r;
}
__device__ __forceinline__ void fma2(unsigned long long& d, unsigned long long a, unsigned long long b){
    asm("fma.rn.f32x2 %0, %1, %2, %0;" : "+l"(d) : "l"(a), "l"(b));
}
__device__ __forceinline__ void unpack2(unsigned long long v, float& lo, float& hi){
    asm("mov.b64 {%0, %1}, %2;" : "=f"(lo), "=f"(hi) : "l"(v));
}

// quad all-gather of a float4 (c-quarter) -> 4 slots of c-pairs
__device__ __forceinline__ void gather4(float4 v, unsigned long long g[4][2]){
    g[0][0] = pack2(v.x, v.y);
    g[0][1] = pack2(v.z, v.w);
    g[1][0] = __shfl_xor_sync(0xffffffffu, g[0][0], 1);
    g[1][1] = __shfl_xor_sync(0xffffffffu, g[0][1], 1);
    g[2][0] = __shfl_xor_sync(0xffffffffu, g[0][0], 2);
    g[2][1] = __shfl_xor_sync(0xffffffffu, g[0][1], 2);
    g[3][0] = __shfl_xor_sync(0xffffffffu, g[1][0], 2);
    g[3][1] = __shfl_xor_sync(0xffffffffu, g[1][1], 2);
}

// acc[dd] += (vector g) dot (matrix Tm rows for d-quarter q)
__device__ __forceinline__ void mat_acc(unsigned long long acc[4],
                                        const unsigned long long g[4][2],
                                        const unsigned long long* Tm, int q){
    #pragma unroll
    for (int dd=0; dd<4; dd++){
        const ulonglong2* row = reinterpret_cast<const ulonglong2*>(Tm + (q*4+dd)*8);
        #pragma unroll
        for (int s=0; s<4; s++){
            ulonglong2 tv = row[q^s];
            fma2(acc[dd], g[s][0], tv.x);
            fma2(acc[dd], g[s][1], tv.y);
        }
    }
}

// ---------------- SIREN body (called from reduce_pass1 extra blocks) ----------------
__device__ void siren_compute(int p, int t,
                              const float* __restrict__ sw0, const float* __restrict__ sb0,
                              const float* __restrict__ sw1, const float* __restrict__ sb1,
                              const float* __restrict__ sw2, const float* __restrict__ sb2,
                              const float* __restrict__ swo, const float* __restrict__ sbo){
    float x0, x1, x2;
    if (p < 64){        int tt=p>>4, a=(p>>2)&3, bb=p&3; x0=f_li(a);   x1=f_li(bb);  x2=f_ti(tt); }
    else if (p < 88){   int q=p-64;  int tt=q>>2, i=q&3; x0=f_li(i);   x1=f_li(i);   x2=f_ti(4+tt); }
    else if (p < 94){   int q=p-88;  int tt=q/3,  i=q%3; x0=f_li(i);   x1=f_li(i+1); x2=f_ti(10+tt); }
    else {              int q=p-94;  int tt=q/3,  i=q%3; x0=f_li(i+1); x1=f_li(i);   x2=f_ti(12+tt); }

    __shared__ float h[NHID];
    if (t < NHID){
        float v = x0*sw0[t] + x1*sw0[NHID+t] + x2*sw0[2*NHID+t] + sb0[t];
        h[t] = sinf(30.0f * v);
    }
    __syncthreads();

    if (t < NHID){
        float a1 = sb1[t];
        #pragma unroll 8
        for (int j=0;j<NHID;j++) a1 = fmaf(h[j], sw1[j*NHID+t], a1);
        a1 = sinf(a1);
        __syncthreads(); h[t] = a1;
    } else __syncthreads();
    __syncthreads();

    if (t < NHID){
        float a2 = sb2[t];
        #pragma unroll 8
        for (int j=0;j<NHID;j++) a2 = fmaf(h[j], sw2[j*NHID+t], a2);
        a2 = sinf(a2);
        __syncthreads(); h[t] = a2;
    } else __syncthreads();
    __syncthreads();

    {
        int o = t;
        float acc = sbo[o];
        #pragma unroll 8
        for (int j=0;j<NHID;j++) acc = fmaf(h[j], swo[j*256+o], acc);
        g_terms[p*256 + o] = acc * INVNORM;
    }
}

// ---------------- reduce pass 1 (+ siren blocks): csums/rsums partials ----------------
__global__ void __launch_bounds__(256, 2)
reduce_pass1(const float* __restrict__ w0, const float* __restrict__ w1,
             const float* __restrict__ w2, const float* __restrict__ w3,
             const float* __restrict__ sw0, const float* __restrict__ sb0,
             const float* __restrict__ sw1, const float* __restrict__ sb1,
             const float* __restrict__ sw2, const float* __restrict__ sb2,
             const float* __restrict__ swo, const float* __restrict__ sbo){
    int b  = blockIdx.y;
    int l  = blockIdx.z;
    if (blockIdx.x >= 8){
        int p = (blockIdx.x - 8)*64 + b*4 + l;
        if (p < 100) siren_compute(p, threadIdx.x, sw0, sb0, sw1, sb1, sw2, sb2, swo, sbo);
        return;
    }
    int jq = blockIdx.x & 3;
    int kh = blockIdx.x >> 2;
    const float* w = (l==0)?w0:(l==1)?w1:(l==2)?w2:w3;

    int t      = threadIdx.x;
    int c4     = t & 3;
    int klocal = t >> 2;
    int lane   = t & 31;
    int warp   = t >> 5;

    const float4* wp = reinterpret_cast<const float4*>(w);
    __shared__ float4 sh[8][16][4][4];   // [warp][jj][kgroup][c4]  32KB

    float4 racc[2];
    #pragma unroll
    for (int kc=0; kc<2; kc++) racc[kc] = make_float4(0.f,0.f,0.f,0.f);

    for (int sub=0; sub<4; sub++){
        int j0 = jq*64 + sub*16;
        float4 csum[16];
        #pragma unroll
        for (int jj=0; jj<16; jj++) csum[jj] = make_float4(0.f,0.f,0.f,0.f);

        #pragma unroll
        for (int kc=0; kc<2; kc++){
            int k = kh*128 + kc*64 + klocal;
            int base = ((b*NN + j0)*NN + k)*4 + c4;
            #pragma unroll
            for (int jj=0; jj<16; jj++){
                float4 v = __ldcs(wp + base + jj*1024);
                racc[kc].x += v.x; racc[kc].y += v.y; racc[kc].z += v.z; racc[kc].w += v.w;
                csum[jj].x += v.x; csum[jj].y += v.y; csum[jj].z += v.z; csum[jj].w += v.w;
            }
        }

        #pragma unroll
        for (int jj=0; jj<16; jj++){
            float4 s = csum[jj];
            s.x += __shfl_xor_sync(0xffffffffu, s.x, 16);
            s.y += __shfl_xor_sync(0xffffffffu, s.y, 16);
            s.z += __shfl_xor_sync(0xffffffffu, s.z, 16);
            s.w += __shfl_xor_sync(0xffffffffu, s.w, 16);
            if (lane < 16) sh[warp][jj][lane >> 2][lane & 3] = s;
        }
        __syncthreads();

        if (t < 64){
            int jj = t >> 2, cc = t & 3;
            float4 s = make_float4(0.f,0.f,0.f,0.f);
            #pragma unroll
            for (int ww=0; ww<8; ww++){
                #pragma unroll
                for (int kg=0; kg<4; kg++){
                    float4 v = sh[ww][jj][kg][cc];
                    s.x += v.x; s.y += v.y; s.z += v.z; s.w += v.w;
                }
            }
            reinterpret_cast<float4*>(g_cpart)[(((kh*NL + l)*NB + b)*NN + j0 + jj)*4 + cc] = s;
        }
        __syncthreads();
    }

    #pragma unroll
    for (int kc=0; kc<2; kc++){
        int k = kh*128 + kc*64 + klocal;
        reinterpret_cast<float4*>(g_rpart)[(((jq*NL + l)*NB + b)*NN + k)*4 + c4] = racc[kc];
    }
}

// ---------------- reduce pass 2: rsums + csums (final) + allsums + sums_b ----------------
__global__ void reduce_pass2(const float* __restrict__ b0, const float* __restrict__ b1,
                             const float* __restrict__ b2, const float* __restrict__ b3){
    int l = blockIdx.x >> 4, b = blockIdx.x & 15;
    const float* bl = (l==0)?b0:(l==1)?b1:(l==2)?b2:b3;
    int k = threadIdx.x;
    int lane = k & 31, warp = k >> 5;
    __shared__ float4 sh2[8][4];
    __shared__ float4 sh3[8][4];

    float4 tot[4];
    #pragma unroll
    for (int c4=0; c4<4; c4++){
        float4 s = make_float4(0.f,0.f,0.f,0.f);
        #pragma unroll
        for (int jq=0; jq<4; jq++){
            float4 v = __ldg(reinterpret_cast<const float4*>(g_rpart) +
                             ((((jq*NL + l)*NB + b)*NN + k)*4 + c4));
            s.x += v.x; s.y += v.y; s.z += v.z; s.w += v.w;
        }
        s.x *= INV256F; s.y *= INV256F; s.z *= INV256F; s.w *= INV256F;
        reinterpret_cast<float4*>(g_rsums)[((l*NB + b)*NN + k)*4 + c4] = s;
        tot[c4] = s;
    }

    {
        const float4* c0 = reinterpret_cast<const float4*>(g_cpart) + ((0*NL + l)*NB + b)*1024;
        const float4* c1 = reinterpret_cast<const float4*>(g_cpart) + ((1*NL + l)*NB + b)*1024;
        float4* cd = reinterpret_cast<float4*>(g_csums) + ((l*NB + b))*1024;
        #pragma unroll
        for (int i=0; i<4; i++){
            int u = i*256 + k;
            float4 a = __ldg(c0 + u), c = __ldg(c1 + u);
            float4 r;
            r.x = (a.x + c.x) * INV256F;
            r.y = (a.y + c.y) * INV256F;
            r.z = (a.z + c.z) * INV256F;
            r.w = (a.w + c.w) * INV256F;
            cd[u] = r;
        }
    }

    #pragma unroll
    for (int c4=0; c4<4; c4++){
        float4 s = tot[c4];
        #pragma unroll
        for (int m=1; m<32; m<<=1){
            s.x += __shfl_xor_sync(0xffffffffu, s.x, m);
            s.y += __shfl_xor_sync(0xffffffffu, s.y, m);
            s.z += __shfl_xor_sync(0xffffffffu, s.z, m);
            s.w += __shfl_xor_sync(0xffffffffu, s.w, m);
        }
        if (lane == 0) sh2[warp][c4] = s;
    }

    {
        const float4* bp = reinterpret_cast<const float4*>(bl) + b*1024;
        float4 s = make_float4(0.f,0.f,0.f,0.f);
        #pragma unroll
        for (int i=0; i<4; i++){
            float4 v = __ldg(bp + i*256 + k);
            s.x += v.x; s.y += v.y; s.z += v.z; s.w += v.w;
        }
        #pragma unroll
        for (int m=4; m<32; m<<=1){
            s.x += __shfl_xor_sync(0xffffffffu, s.x, m);
            s.y += __shfl_xor_sync(0xffffffffu, s.y, m);
            s.z += __shfl_xor_sync(0xffffffffu, s.z, m);
            s.w += __shfl_xor_sync(0xffffffffu, s.w, m);
        }
        if (lane < 4) sh3[warp][lane] = s;
    }
    __syncthreads();

    if (k < 4){
        float4 s = make_float4(0.f,0.f,0.f,0.f);
        #pragma unroll
        for (int ww=0; ww<8; ww++){
            float4 v = sh2[ww][k];
            s.x += v.x; s.y += v.y; s.z += v.z; s.w += v.w;
        }
        int cb = k*4;
        g_allsums[b*64 + (cb+0)*4 + l] = s.x * INV256F;
        g_allsums[b*64 + (cb+1)*4 + l] = s.y * INV256F;
        g_allsums[b*64 + (cb+2)*4 + l] = s.z * INV256F;
        g_allsums[b*64 + (cb+3)*4 + l] = s.w * INV256F;
    } else if (k >= 8 && k < 12){
        int c4 = k - 8;
        float4 s = make_float4(0.f,0.f,0.f,0.f);
        #pragma unroll
        for (int ww=0; ww<8; ww++){
            float4 v = sh3[ww][c4];
            s.x += v.x; s.y += v.y; s.z += v.z; s.w += v.w;
        }
        int cb = c4*4;
        g_sumsb[b*64 + (cb+0)*4 + l] = s.x * INV256F;
        g_sumsb[b*64 + (cb+1)*4 + l] = s.y * INV256F;
        g_sumsb[b*64 + (cb+2)*4 + l] = s.z * INV256F;
        g_sumsb[b*64 + (cb+3)*4 + l] = s.w * INV256F;
    }
}

// ---------------- colrow: rowterm + ob (+ basew for main) ----------------
__global__ void __launch_bounds__(256, 2)
colrow_kernel(const float* __restrict__ b0, const float* __restrict__ b1,
              const float* __restrict__ b2, const float* __restrict__ b3,
              float* __restrict__ out){
    int rem = blockIdx.x;
    int l = rem >> 6, b = (rem >> 2) & 15, xt = rem & 3;
    int t = threadIdx.x, q = t & 3;
    int x = xt*64 + (t >> 2);

    __shared__ unsigned long long Tt[6*128];
    __shared__ float sh_base[16];

    int terms[6];
    terms[0] = 64 + l; terms[1] = 76 + l;      // rowterm: wrow(v0=rs), w_b(v1=bv)
    terms[2] = 80 + l; terms[3] = 84 + l;      // ob: b_wcol(v0=rs), bb(v1=bv)
    int nm = 4;
    if (l < 3){ terms[4] = 88 + l; terms[5] = 91 + l; nm = 6; }
    if (t < 128){
        int d = t >> 3, c2 = t & 7;
        for (int m=0; m<nm; m++){
            float lo = __ldg(&g_terms[terms[m]*256 + (2*c2  )*16 + d]);
            float hi = __ldg(&g_terms[terms[m]*256 + (2*c2+1)*16 + d]);
            Tt[m*128 + t] = pack2(lo, hi);
        }
    } else if (t >= 208 && t < 240){
        int wb = (t >= 224);
        int d = t - (wb ? 224 : 208);
        int off = wb ? 32 : 0;
        float acc = 0.f;
        #pragma unroll
        for (int lp=0; lp<NL; lp++){
            #pragma unroll
            for (int c=0; c<NC; c++){
                float as  = g_allsums[b*64 + c*4 + lp];
                float sbv = g_sumsb[b*64 + c*4 + lp];
                int e = c*16 + d;
                acc = fmaf(as,  g_terms[(off      + l*4 + lp)*256 + e], acc);
                acc = fmaf(sbv, g_terms[(off + 16 + l*4 + lp)*256 + e], acc);
            }
        }
        if (wb) sh_base[d] = acc;
        else    g_basew[(l*NB + b)*NC + d] = acc;
    }
    __syncthreads();

    const float4* csp = reinterpret_cast<const float4*>(g_csums);
    const float4* rsp = reinterpret_cast<const float4*>(g_rsums);
    float4 basev = *reinterpret_cast<const float4*>(&sh_base[q*4]);

    const float* blp = (l==0)?b0:(l==1)?b1:(l==2)?b2:b3;
    float4 v0 = __ldg(rsp + ((l*NB + b)*NN + x)*4 + q);
    float4 v1 = __ldg(reinterpret_cast<const float4*>(blp) + (b*NN + x)*4 + q);
    unsigned long long g0[4][2], g1[4][2];
    gather4(v0, g0);
    gather4(v1, g1);

    unsigned long long accA[4] = {0ull,0ull,0ull,0ull};   // rowterm
    unsigned long long accB[4] = {0ull,0ull,0ull,0ull};   // ob
    mat_acc(accA, g0, &Tt[0],   q);
    mat_acc(accA, g1, &Tt[128], q);
    mat_acc(accB, g0, &Tt[256], q);
    mat_acc(accB, g1, &Tt[384], q);
    if (l < 3){
        float4 v2 = __ldg(csp + (((l+1)*NB + b)*NN + x)*4 + q);
        unsigned long long g2[4][2];
        gather4(v2, g2);
        mat_acc(accA, g2, &Tt[512], q);
        mat_acc(accB, g2, &Tt[640], q);
    }

    float4 resA;
    { float lo, hi; unpack2(accA[0], lo, hi); resA.x = lo + hi; }
    { float lo, hi; unpack2(accA[1], lo, hi); resA.y = lo + hi; }
    { float lo, hi; unpack2(accA[2], lo, hi); resA.z = lo + hi; }
    { float lo, hi; unpack2(accA[3], lo, hi); resA.w = lo + hi; }
    reinterpret_cast<float4*>(g_rowterm)[((l*NB + b)*NN + x)*4 + q] = resA;

    float4 resB;
    { float lo, hi; unpack2(accB[0], lo, hi); resB.x = lo + hi + basev.x; }
    { float lo, hi; unpack2(accB[1], lo, hi); resB.y = lo + hi + basev.y; }
    { float lo, hi; unpack2(accB[2], lo, hi); resB.z = lo + hi + basev.z; }
    { float lo, hi; unpack2(accB[3], lo, hi); resB.w = lo + hi + basev.w; }
    reinterpret_cast<float4*>(out + (size_t)l*OW_STRIDE + OB_OFF)[(b*NN + x)*4 + q] = resB;
}

// ---------------- main output pass: 8 j-rows per block, streaming loads/stores ----------------
// grid (32, 16, 4), 256 threads. Threads 128..255 build shcol (8 rows x 16 d, 1 value each).
__global__ void __launch_bounds__(256, 2)
main_kernel(const float* __restrict__ w0, const float* __restrict__ w1,
            const float* __restrict__ w2, const float* __restrict__ w3,
            const float* __restrict__ b0, const float* __restrict__ b1,
            const float* __restrict__ b2, const float* __restrict__ b3,
            float* __restrict__ out){
    int l  = 3 - (int)blockIdx.z;
    int b  = 15 - (int)blockIdx.y;
    int jx = 31 - (int)blockIdx.x;
    int j0 = jx*8;
    int t = threadIdx.x;
    int q = t & 3;
    const float* w = (l==0)?w0:(l==1)?w1:(l==2)?w2:w3;

    const float4* wrow = reinterpret_cast<const float4*>(w) + (size_t)(b*NN + j0)*1024;
    const float4* rrow = reinterpret_cast<const float4*>(g_rowterm) + (size_t)(l*NB + b)*1024;
    float4*       orow = reinterpret_cast<float4*>(out + (size_t)l*OW_STRIDE) + (size_t)(b*NN + j0)*1024;

    // prologue loads: rowterm (reused across all 8 j) + w pipeline depth 2
    float4 rv0 = __ldg(rrow + 0*256 + t);
    float4 rv1 = __ldg(rrow + 1*256 + t);
    float4 rv2 = __ldg(rrow + 2*256 + t);
    float4 rv3 = __ldg(rrow + 3*256 + t);
    float4 wvA = __ldcs(wrow + t);
    float4 wvB = __ldcs(wrow + 256 + t);

    __shared__ unsigned long long Tt_s[128];   // [d][c2] c-paired transposed T
    __shared__ float shcol[128];               // colterm rows j0..j0+7
    if (t < 128){
        int d = t >> 3, c2 = t & 7;
        float lo = __ldg(&g_terms[(72+l)*256 + (2*c2  )*16 + d]);
        float hi = __ldg(&g_terms[(72+l)*256 + (2*c2+1)*16 + d]);
        Tt_s[t] = pack2(lo, hi);
    } else {
        int r = t - 128;                // 0..127
        int jj = r >> 4, d = r & 15;
        int j = j0 + jj;
        float acc = __ldg(&g_basew[(l*NB + b)*NC + d]);
        const float* cs = &g_csums[((l*NB + b)*NN + j)*NC];
        const float* T1 = &g_terms[(68 + l)*256];          // t_w_wcol
        #pragma unroll
        for (int c=0; c<NC; c++) acc = fmaf(cs[c], T1[c*16 + d], acc);
        if (l > 0){
            const float* rs  = &g_rsums[(((l-1)*NB + b)*NN + j)*NC];
            const float* bp  = ((l-1)==0?b0:(l-1)==1?b1:(l-1)==2?b2:b3) + (b*NN + j)*NC;
            const float* Tm0 = &g_terms[(94 + (l-1))*256]; // t_w_wm1
            const float* Tm1 = &g_terms[(97 + (l-1))*256]; // t_w_bm1
            #pragma unroll
            for (int c=0; c<NC; c++){
                acc = fmaf(rs[c], Tm0[c*16 + d], acc);
                acc = fmaf(bp[c], Tm1[c*16 + d], acc);
            }
        }
        shcol[r] = acc;
    }
    __syncthreads();

    int q1 = q^1, q2 = q^2, q3 = q^3;
    ulonglong2 TT[4][4];
    #pragma unroll
    for (int dd=0; dd<4; dd++){
        const ulonglong2* row = reinterpret_cast<const ulonglong2*>(&Tt_s[(q*4+dd)*8]);
        TT[dd][0] = row[q];
        TT[dd][1] = row[q1];
        TT[dd][2] = row[q2];
        TT[dd][3] = row[q3];
    }

    #pragma unroll 4
    for (int u=0; u<32; u++){
        int kc = u & 3;
        int jj = u >> 2;

        float4 wvC;
        if (u < 30) wvC = __ldcs(wrow + (u+2)*256 + t);

        unsigned long long a0 = pack2(wvA.x, wvA.y);
        unsigned long long a1 = pack2(wvA.z, wvA.w);
        unsigned long long c0 = __shfl_xor_sync(0xffffffffu, a0, 1);
        unsigned long long c1 = __shfl_xor_sync(0xffffffffu, a1, 1);
        unsigned long long e0 = __shfl_xor_sync(0xffffffffu, a0, 2);
        unsigned long long e1 = __shfl_xor_sync(0xffffffffu, a1, 2);
        unsigned long long f0 = __shfl_xor_sync(0xffffffffu, c0, 2);
        unsigned long long f1 = __shfl_xor_sync(0xffffffffu, c1, 2);

        unsigned long long acc[4] = {0ull, 0ull, 0ull, 0ull};
        #pragma unroll
        for (int dd=0; dd<4; dd++){
            fma2(acc[dd], a0, TT[dd][0].x);
            fma2(acc[dd], a1, TT[dd][0].y);
            fma2(acc[dd], c0, TT[dd][1].x);
            fma2(acc[dd], c1, TT[dd][1].y);
            fma2(acc[dd], e0, TT[dd][2].x);
            fma2(acc[dd], e1, TT[dd][2].y);
            fma2(acc[dd], f0, TT[dd][3].x);
            fma2(acc[dd], f1, TT[dd][3].y);
        }

        float4 colv = *reinterpret_cast<const float4*>(&shcol[jj*16 + q*4]);
        float4 rv = (kc==0) ? rv0 : (kc==1) ? rv1 : (kc==2) ? rv2 : rv3;
        float4 res;
        { float lo, hi; unpack2(acc[0], lo, hi); res.x = lo + hi; }
        { float lo, hi; unpack2(acc[1], lo, hi); res.y = lo + hi; }
        { float lo, hi; unpack2(acc[2], lo, hi); res.z = lo + hi; }
        { float lo, hi; unpack2(acc[3], lo, hi); res.w = lo + hi; }
        res.x += colv.x + rv.x;
        res.y += colv.y + rv.y;
        res.z += colv.z + rv.z;
        res.w += colv.w + rv.w;
        __stcs(orow + u*256 + t, res);

        wvA = wvB; wvB = wvC;
    }
}

// ---------------- launch ----------------
extern "C" void kernel_launch(void* const* d_in, const int* in_sizes, int n_in,
                              void* d_out, int out_size){
    (void)n_in; (void)out_size;
    const float* w[4]; const float* bb[4];
    int wi = 0, bi = 0;
    for (int i = 0; i < 8; i++){
        if (in_sizes[i] > 1000000) w[wi++] = (const float*)d_in[i];
        else                       bb[bi++] = (const float*)d_in[i];
    }
    const float* sw0 = (const float*)d_in[8];
    const float* sb0 = (const float*)d_in[9];
    const float* sw1 = (const float*)d_in[10];
    const float* sb1 = (const float*)d_in[11];
    const float* sw2 = (const float*)d_in[12];
    const float* sb2 = (const float*)d_in[13];
    const float* swo = (const float*)d_in[14];
    const float* sbo = (const float*)d_in[15];
    float* out = (float*)d_out;

    reduce_pass1<<<dim3(10, NB, NL), 256>>>(w[0], w[1], w[2], w[3],
                                            sw0, sb0, sw1, sb1, sw2, sb2, swo, sbo);
    reduce_pass2<<<64, 256>>>(bb[0], bb[1], bb[2], bb[3]);
    colrow_kernel<<<256, 256>>>(bb[0], bb[1], bb[2], bb[3], out);
    main_kernel<<<dim3(32, NB, NL), 256>>>(w[0], w[1], w[2], w[3],
                                           bb[0], bb[1], bb[2], bb[3], out);
}

// round 15
// speedup vs baseline: 1.3307x; 1.3307x over previous
#include <cuda_runtime.h>
#include <math.h>

#define NL 4
#define NB 16
#define NN 256
#define NC 16
#define NHID 64
#define INV256F (1.0f/256.0f)
#define INVNORM 0.06454972243679028f   /* 1/sqrt(240) */
#define OW_STRIDE 16842752             /* per-layer stride in d_out (ow + ob) */
#define OB_OFF    16777216             /* offset of ob within a layer chunk */

// ---------------- scratch (device globals; no allocs) ----------------
__device__ float g_terms[100*256];          // 100 siren points x (16c x 16d)
__device__ float g_rsums[NL*NB*NN*NC];      // mean over j  -> [l][b][k][c]
__device__ float g_csums[NL*NB*NN*NC];      // mean over k  -> [l][b][j][c]
__device__ float g_rpart[4*NL*NB*NN*NC];    // 4 j-quarter partial sums over j
__device__ float g_cpart[2*NL*NB*NN*NC];    // 2 k-half partial sums over k
__device__ float g_allsums[NB*NC*NL];       // [b][c][l]
__device__ float g_sumsb[NB*NC*NL];         // [b][c][l]
__device__ float g_basew[NL*NB*NC];         // [l][b][d]
__device__ float g_rowterm[NL*NB*NN*NC];    // [l][b][k][d]

// g_terms point layout:
// global: t*16 + a*4 + b   (t=0..3)
// diag:   64 + t*4 + i     (t=0..5)
// p1:     88 + t*3 + i     (t=0..1, i=0..2)
// m1:     94 + t*3 + i

__device__ __forceinline__ float f_li(int i){ return -1.0f + (2.0f/3.0f)*i; }
__device__ __forceinline__ float f_ti(int m){ return -1.0f + (2.0f/13.0f)*m; }

__device__ __forceinline__ unsigned long long pack2(float lo, float hi){
    unsigned long long r;
    asm("mov.b64 %0, {%1, %2};" : "=l"(r) : "f"(lo), "f"(hi));
    return r;
}
__device__ __forceinline__ void fma2(unsigned long long& d, unsigned long long a, unsigned long long b){
    asm("fma.rn.f32x2 %0, %1, %2, %0;" : "+l"(d) : "l"(a), "l"(b));
}
__device__ __forceinline__ void unpack2(unsigned long long v, float& lo, float& hi){
    asm("mov.b64 {%0, %1}, %2;" : "=f"(lo), "=f"(hi) : "l"(v));
}

// quad all-gather of a float4 (c-quarter) -> 4 slots of c-pairs
__device__ __forceinline__ void gather4(float4 v, unsigned long long g[4][2]){
    g[0][0] = pack2(v.x, v.y);
    g[0][1] = pack2(v.z, v.w);
    g[1][0] = __shfl_xor_sync(0xffffffffu, g[0][0], 1);
    g[1][1] = __shfl_xor_sync(0xffffffffu, g[0][1], 1);
    g[2][0] = __shfl_xor_sync(0xffffffffu, g[0][0], 2);
    g[2][1] = __shfl_xor_sync(0xffffffffu, g[0][1], 2);
    g[3][0] = __shfl_xor_sync(0xffffffffu, g[1][0], 2);
    g[3][1] = __shfl_xor_sync(0xffffffffu, g[1][1], 2);
}

// acc[dd] += (vector g) dot (matrix Tm rows for d-quarter q)
__device__ __forceinline__ void mat_acc(unsigned long long acc[4],
                                        const unsigned long long g[4][2],
                                        const unsigned long long* Tm, int q){
    #pragma unroll
    for (int dd=0; dd<4; dd++){
        const ulonglong2* row = reinterpret_cast<const ulonglong2*>(Tm + (q*4+dd)*8);
        #pragma unroll
        for (int s=0; s<4; s++){
            ulonglong2 tv = row[q^s];
            fma2(acc[dd], g[s][0], tv.x);
            fma2(acc[dd], g[s][1], tv.y);
        }
    }
}

// ---------------- SIREN body (called from reduce_pass1 extra blocks) ----------------
__device__ void siren_compute(int p, int t,
                              const float* __restrict__ sw0, const float* __restrict__ sb0,
                              const float* __restrict__ sw1, const float* __restrict__ sb1,
                              const float* __restrict__ sw2, const float* __restrict__ sb2,
                              const float* __restrict__ swo, const float* __restrict__ sbo){
    float x0, x1, x2;
    if (p < 64){        int tt=p>>4, a=(p>>2)&3, bb=p&3; x0=f_li(a);   x1=f_li(bb);  x2=f_ti(tt); }
    else if (p < 88){   int q=p-64;  int tt=q>>2, i=q&3; x0=f_li(i);   x1=f_li(i);   x2=f_ti(4+tt); }
    else if (p < 94){   int q=p-88;  int tt=q/3,  i=q%3; x0=f_li(i);   x1=f_li(i+1); x2=f_ti(10+tt); }
    else {              int q=p-94;  int tt=q/3,  i=q%3; x0=f_li(i+1); x1=f_li(i);   x2=f_ti(12+tt); }

    __shared__ float h[NHID];
    if (t < NHID){
        float v = x0*sw0[t] + x1*sw0[NHID+t] + x2*sw0[2*NHID+t] + sb0[t];
        h[t] = sinf(30.0f * v);
    }
    __syncthreads();

    if (t < NHID){
        float a1 = sb1[t];
        #pragma unroll 8
        for (int j=0;j<NHID;j++) a1 = fmaf(h[j], sw1[j*NHID+t], a1);
        a1 = sinf(a1);
        __syncthreads(); h[t] = a1;
    } else __syncthreads();
    __syncthreads();

    if (t < NHID){
        float a2 = sb2[t];
        #pragma unroll 8
        for (int j=0;j<NHID;j++) a2 = fmaf(h[j], sw2[j*NHID+t], a2);
        a2 = sinf(a2);
        __syncthreads(); h[t] = a2;
    } else __syncthreads();
    __syncthreads();

    {
        int o = t;
        float acc = sbo[o];
        #pragma unroll 8
        for (int j=0;j<NHID;j++) acc = fmaf(h[j], swo[j*256+o], acc);
        g_terms[p*256 + o] = acc * INVNORM;
    }
}

// ---------------- reduce pass 1 (+ siren blocks): csums/rsums partials ----------------
__global__ void __launch_bounds__(256, 2)
reduce_pass1(const float* __restrict__ w0, const float* __restrict__ w1,
             const float* __restrict__ w2, const float* __restrict__ w3,
             const float* __restrict__ sw0, const float* __restrict__ sb0,
             const float* __restrict__ sw1, const float* __restrict__ sb1,
             const float* __restrict__ sw2, const float* __restrict__ sb2,
             const float* __restrict__ swo, const float* __restrict__ sbo){
    int b  = blockIdx.y;
    int l  = blockIdx.z;
    if (blockIdx.x >= 8){
        int p = (blockIdx.x - 8)*64 + b*4 + l;
        if (p < 100) siren_compute(p, threadIdx.x, sw0, sb0, sw1, sb1, sw2, sb2, swo, sbo);
        return;
    }
    int jq = blockIdx.x & 3;
    int kh = blockIdx.x >> 2;
    const float* w = (l==0)?w0:(l==1)?w1:(l==2)?w2:w3;

    int t      = threadIdx.x;
    int c4     = t & 3;
    int klocal = t >> 2;
    int lane   = t & 31;
    int warp   = t >> 5;

    const float4* wp = reinterpret_cast<const float4*>(w);
    __shared__ float4 sh[8][16][4][4];   // [warp][jj][kgroup][c4]  32KB

    float4 racc[2];
    #pragma unroll
    for (int kc=0; kc<2; kc++) racc[kc] = make_float4(0.f,0.f,0.f,0.f);

    for (int sub=0; sub<4; sub++){
        int j0 = jq*64 + sub*16;
        float4 csum[16];
        #pragma unroll
        for (int jj=0; jj<16; jj++) csum[jj] = make_float4(0.f,0.f,0.f,0.f);

        #pragma unroll
        for (int kc=0; kc<2; kc++){
            int k = kh*128 + kc*64 + klocal;
            int base = ((b*NN + j0)*NN + k)*4 + c4;
            #pragma unroll
            for (int jj=0; jj<16; jj++){
                float4 v = __ldg(wp + base + jj*1024);
                racc[kc].x += v.x; racc[kc].y += v.y; racc[kc].z += v.z; racc[kc].w += v.w;
                csum[jj].x += v.x; csum[jj].y += v.y; csum[jj].z += v.z; csum[jj].w += v.w;
            }
        }

        #pragma unroll
        for (int jj=0; jj<16; jj++){
            float4 s = csum[jj];
            s.x += __shfl_xor_sync(0xffffffffu, s.x, 16);
            s.y += __shfl_xor_sync(0xffffffffu, s.y, 16);
            s.z += __shfl_xor_sync(0xffffffffu, s.z, 16);
            s.w += __shfl_xor_sync(0xffffffffu, s.w, 16);
            if (lane < 16) sh[warp][jj][lane >> 2][lane & 3] = s;
        }
        __syncthreads();

        if (t < 64){
            int jj = t >> 2, cc = t & 3;
            float4 s = make_float4(0.f,0.f,0.f,0.f);
            #pragma unroll
            for (int ww=0; ww<8; ww++){
                #pragma unroll
                for (int kg=0; kg<4; kg++){
                    float4 v = sh[ww][jj][kg][cc];
                    s.x += v.x; s.y += v.y; s.z += v.z; s.w += v.w;
                }
            }
            reinterpret_cast<float4*>(g_cpart)[(((kh*NL + l)*NB + b)*NN + j0 + jj)*4 + cc] = s;
        }
        __syncthreads();
    }

    #pragma unroll
    for (int kc=0; kc<2; kc++){
        int k = kh*128 + kc*64 + klocal;
        reinterpret_cast<float4*>(g_rpart)[(((jq*NL + l)*NB + b)*NN + k)*4 + c4] = racc[kc];
    }
}

// ---------------- reduce pass 2: rsums + csums (final) + allsums + sums_b ----------------
__global__ void reduce_pass2(const float* __restrict__ b0, const float* __restrict__ b1,
                             const float* __restrict__ b2, const float* __restrict__ b3){
    int l = blockIdx.x >> 4, b = blockIdx.x & 15;
    const float* bl = (l==0)?b0:(l==1)?b1:(l==2)?b2:b3;
    int k = threadIdx.x;
    int lane = k & 31, warp = k >> 5;
    __shared__ float4 sh2[8][4];
    __shared__ float4 sh3[8][4];

    float4 tot[4];
    #pragma unroll
    for (int c4=0; c4<4; c4++){
        float4 s = make_float4(0.f,0.f,0.f,0.f);
        #pragma unroll
        for (int jq=0; jq<4; jq++){
            float4 v = __ldg(reinterpret_cast<const float4*>(g_rpart) +
                             ((((jq*NL + l)*NB + b)*NN + k)*4 + c4));
            s.x += v.x; s.y += v.y; s.z += v.z; s.w += v.w;
        }
        s.x *= INV256F; s.y *= INV256F; s.z *= INV256F; s.w *= INV256F;
        reinterpret_cast<float4*>(g_rsums)[((l*NB + b)*NN + k)*4 + c4] = s;
        tot[c4] = s;
    }

    {
        const float4* c0 = reinterpret_cast<const float4*>(g_cpart) + ((0*NL + l)*NB + b)*1024;
        const float4* c1 = reinterpret_cast<const float4*>(g_cpart) + ((1*NL + l)*NB + b)*1024;
        float4* cd = reinterpret_cast<float4*>(g_csums) + ((l*NB + b))*1024;
        #pragma unroll
        for (int i=0; i<4; i++){
            int u = i*256 + k;
            float4 a = __ldg(c0 + u), c = __ldg(c1 + u);
            float4 r;
            r.x = (a.x + c.x) * INV256F;
            r.y = (a.y + c.y) * INV256F;
            r.z = (a.z + c.z) * INV256F;
            r.w = (a.w + c.w) * INV256F;
            cd[u] = r;
        }
    }

    #pragma unroll
    for (int c4=0; c4<4; c4++){
        float4 s = tot[c4];
        #pragma unroll
        for (int m=1; m<32; m<<=1){
            s.x += __shfl_xor_sync(0xffffffffu, s.x, m);
            s.y += __shfl_xor_sync(0xffffffffu, s.y, m);
            s.z += __shfl_xor_sync(0xffffffffu, s.z, m);
            s.w += __shfl_xor_sync(0xffffffffu, s.w, m);
        }
        if (lane == 0) sh2[warp][c4] = s;
    }

    {
        const float4* bp = reinterpret_cast<const float4*>(bl) + b*1024;
        float4 s = make_float4(0.f,0.f,0.f,0.f);
        #pragma unroll
        for (int i=0; i<4; i++){
            float4 v = __ldg(bp + i*256 + k);
            s.x += v.x; s.y += v.y; s.z += v.z; s.w += v.w;
        }
        #pragma unroll
        for (int m=4; m<32; m<<=1){
            s.x += __shfl_xor_sync(0xffffffffu, s.x, m);
            s.y += __shfl_xor_sync(0xffffffffu, s.y, m);
            s.z += __shfl_xor_sync(0xffffffffu, s.z, m);
            s.w += __shfl_xor_sync(0xffffffffu, s.w, m);
        }
        if (lane < 4) sh3[warp][lane] = s;
    }
    __syncthreads();

    if (k < 4){
        float4 s = make_float4(0.f,0.f,0.f,0.f);
        #pragma unroll
        for (int ww=0; ww<8; ww++){
            float4 v = sh2[ww][k];
            s.x += v.x; s.y += v.y; s.z += v.z; s.w += v.w;
        }
        int cb = k*4;
        g_allsums[b*64 + (cb+0)*4 + l] = s.x * INV256F;
        g_allsums[b*64 + (cb+1)*4 + l] = s.y * INV256F;
        g_allsums[b*64 + (cb+2)*4 + l] = s.z * INV256F;
        g_allsums[b*64 + (cb+3)*4 + l] = s.w * INV256F;
    } else if (k >= 8 && k < 12){
        int c4 = k - 8;
        float4 s = make_float4(0.f,0.f,0.f,0.f);
        #pragma unroll
        for (int ww=0; ww<8; ww++){
            float4 v = sh3[ww][c4];
            s.x += v.x; s.y += v.y; s.z += v.z; s.w += v.w;
        }
        int cb = c4*4;
        g_sumsb[b*64 + (cb+0)*4 + l] = s.x * INV256F;
        g_sumsb[b*64 + (cb+1)*4 + l] = s.y * INV256F;
        g_sumsb[b*64 + (cb+2)*4 + l] = s.z * INV256F;
        g_sumsb[b*64 + (cb+3)*4 + l] = s.w * INV256F;
    }
}

// ---------------- colrow: rowterm + ob (+ basew for main) ----------------
__global__ void __launch_bounds__(256, 2)
colrow_kernel(const float* __restrict__ b0, const float* __restrict__ b1,
              const float* __restrict__ b2, const float* __restrict__ b3,
              float* __restrict__ out){
    int rem = blockIdx.x;
    int l = rem >> 6, b = (rem >> 2) & 15, xt = rem & 3;
    int t = threadIdx.x, q = t & 3;
    int x = xt*64 + (t >> 2);

    __shared__ unsigned long long Tt[6*128];
    __shared__ float sh_base[16];

    int terms[6];
    terms[0] = 64 + l; terms[1] = 76 + l;      // rowterm: wrow(v0=rs), w_b(v1=bv)
    terms[2] = 80 + l; terms[3] = 84 + l;      // ob: b_wcol(v0=rs), bb(v1=bv)
    int nm = 4;
    if (l < 3){ terms[4] = 88 + l; terms[5] = 91 + l; nm = 6; }
    if (t < 128){
        int d = t >> 3, c2 = t & 7;
        for (int m=0; m<nm; m++){
            float lo = __ldg(&g_terms[terms[m]*256 + (2*c2  )*16 + d]);
            float hi = __ldg(&g_terms[terms[m]*256 + (2*c2+1)*16 + d]);
            Tt[m*128 + t] = pack2(lo, hi);
        }
    } else if (t >= 208 && t < 240){
        int wb = (t >= 224);
        int d = t - (wb ? 224 : 208);
        int off = wb ? 32 : 0;
        float acc = 0.f;
        #pragma unroll
        for (int lp=0; lp<NL; lp++){
            #pragma unroll
            for (int c=0; c<NC; c++){
                float as  = g_allsums[b*64 + c*4 + lp];
                float sbv = g_sumsb[b*64 + c*4 + lp];
                int e = c*16 + d;
                acc = fmaf(as,  g_terms[(off      + l*4 + lp)*256 + e], acc);
                acc = fmaf(sbv, g_terms[(off + 16 + l*4 + lp)*256 + e], acc);
            }
        }
        if (wb) sh_base[d] = acc;
        else    g_basew[(l*NB + b)*NC + d] = acc;
    }
    __syncthreads();

    const float4* csp = reinterpret_cast<const float4*>(g_csums);
    const float4* rsp = reinterpret_cast<const float4*>(g_rsums);
    float4 basev = *reinterpret_cast<const float4*>(&sh_base[q*4]);

    const float* blp = (l==0)?b0:(l==1)?b1:(l==2)?b2:b3;
    float4 v0 = __ldg(rsp + ((l*NB + b)*NN + x)*4 + q);
    float4 v1 = __ldg(reinterpret_cast<const float4*>(blp) + (b*NN + x)*4 + q);
    unsigned long long g0[4][2], g1[4][2];
    gather4(v0, g0);
    gather4(v1, g1);

    unsigned long long accA[4] = {0ull,0ull,0ull,0ull};   // rowterm
    unsigned long long accB[4] = {0ull,0ull,0ull,0ull};   // ob
    mat_acc(accA, g0, &Tt[0],   q);
    mat_acc(accA, g1, &Tt[128], q);
    mat_acc(accB, g0, &Tt[256], q);
    mat_acc(accB, g1, &Tt[384], q);
    if (l < 3){
        float4 v2 = __ldg(csp + (((l+1)*NB + b)*NN + x)*4 + q);
        unsigned long long g2[4][2];
        gather4(v2, g2);
        mat_acc(accA, g2, &Tt[512], q);
        mat_acc(accB, g2, &Tt[640], q);
    }

    float4 resA;
    { float lo, hi; unpack2(accA[0], lo, hi); resA.x = lo + hi; }
    { float lo, hi; unpack2(accA[1], lo, hi); resA.y = lo + hi; }
    { float lo, hi; unpack2(accA[2], lo, hi); resA.z = lo + hi; }
    { float lo, hi; unpack2(accA[3], lo, hi); resA.w = lo + hi; }
    reinterpret_cast<float4*>(g_rowterm)[((l*NB + b)*NN + x)*4 + q] = resA;

    float4 resB;
    { float lo, hi; unpack2(accB[0], lo, hi); resB.x = lo + hi + basev.x; }
    { float lo, hi; unpack2(accB[1], lo, hi); resB.y = lo + hi + basev.y; }
    { float lo, hi; unpack2(accB[2], lo, hi); resB.z = lo + hi + basev.z; }
    { float lo, hi; unpack2(accB[3], lo, hi); resB.w = lo + hi + basev.w; }
    reinterpret_cast<float4*>(out + (size_t)l*OW_STRIDE + OB_OFF)[(b*NN + x)*4 + q] = resB;
}

// ---------------- main output pass: 4 j-rows per block, colterm computed in prologue ----------------
// grid (64, 16, 4), 256 threads. Threads 192..255 build shcol for the 4 rows.
__global__ void __launch_bounds__(256, 2)
main_kernel(const float* __restrict__ w0, const float* __restrict__ w1,
            const float* __restrict__ w2, const float* __restrict__ w3,
            const float* __restrict__ b0, const float* __restrict__ b1,
            const float* __restrict__ b2, const float* __restrict__ b3,
            float* __restrict__ out){
    int l  = 3 - (int)blockIdx.z;
    int b  = 15 - (int)blockIdx.y;
    int jx = 63 - (int)blockIdx.x;
    int j0 = jx*4;
    int t = threadIdx.x;
    int q = t & 3;
    const float* w = (l==0)?w0:(l==1)?w1:(l==2)?w2:w3;

    const float4* wrow = reinterpret_cast<const float4*>(w) + (size_t)(b*NN + j0)*1024;
    const float4* rrow = reinterpret_cast<const float4*>(g_rowterm) + (size_t)(l*NB + b)*1024;
    float4*       orow = reinterpret_cast<float4*>(out + (size_t)l*OW_STRIDE) + (size_t)(b*NN + j0)*1024;

    // prologue loads: rowterm (reused across all 4 j) + w pipeline depth 2
    float4 rv0 = __ldg(rrow + 0*256 + t);
    float4 rv1 = __ldg(rrow + 1*256 + t);
    float4 rv2 = __ldg(rrow + 2*256 + t);
    float4 rv3 = __ldg(rrow + 3*256 + t);
    float4 wvA = __ldg(wrow + t);
    float4 wvB = __ldg(wrow + 256 + t);

    __shared__ unsigned long long Tt_s[128];   // [d][c2] c-paired transposed T
    __shared__ float shcol[64];                // colterm rows j0..j0+3
    if (t < 128){
        int d = t >> 3, c2 = t & 7;
        float lo = __ldg(&g_terms[(72+l)*256 + (2*c2  )*16 + d]);
        float hi = __ldg(&g_terms[(72+l)*256 + (2*c2+1)*16 + d]);
        Tt_s[t] = pack2(lo, hi);
    } else if (t >= 192){
        int r = t - 192;                // 0..63
        int jj = r >> 4, d = r & 15;
        int j = j0 + jj;
        float acc = __ldg(&g_basew[(l*NB + b)*NC + d]);
        const float* cs = &g_csums[((l*NB + b)*NN + j)*NC];
        const float* T1 = &g_terms[(68 + l)*256];          // t_w_wcol
        #pragma unroll
        for (int c=0; c<NC; c++) acc = fmaf(cs[c], T1[c*16 + d], acc);
        if (l > 0){
            const float* rs  = &g_rsums[(((l-1)*NB + b)*NN + j)*NC];
            const float* bp  = ((l-1)==0?b0:(l-1)==1?b1:(l-1)==2?b2:b3) + (b*NN + j)*NC;
            const float* Tm0 = &g_terms[(94 + (l-1))*256]; // t_w_wm1
            const float* Tm1 = &g_terms[(97 + (l-1))*256]; // t_w_bm1
            #pragma unroll
            for (int c=0; c<NC; c++){
                acc = fmaf(rs[c], Tm0[c*16 + d], acc);
                acc = fmaf(bp[c], Tm1[c*16 + d], acc);
            }
        }
        shcol[r] = acc;
    }
    __syncthreads();

    int q1 = q^1, q2 = q^2, q3 = q^3;
    ulonglong2 TT[4][4];
    #pragma unroll
    for (int dd=0; dd<4; dd++){
        const ulonglong2* row = reinterpret_cast<const ulonglong2*>(&Tt_s[(q*4+dd)*8]);
        TT[dd][0] = row[q];
        TT[dd][1] = row[q1];
        TT[dd][2] = row[q2];
        TT[dd][3] = row[q3];
    }

    #pragma unroll
    for (int u=0; u<16; u++){
        int kc = u & 3;
        int jj = u >> 2;

        float4 wvC;
        if (u < 14) wvC = __ldg(wrow + (u+2)*256 + t);

        unsigned long long a0 = pack2(wvA.x, wvA.y);
        unsigned long long a1 = pack2(wvA.z, wvA.w);
        unsigned long long c0 = __shfl_xor_sync(0xffffffffu, a0, 1);
        unsigned long long c1 = __shfl_xor_sync(0xffffffffu, a1, 1);
        unsigned long long e0 = __shfl_xor_sync(0xffffffffu, a0, 2);
        unsigned long long e1 = __shfl_xor_sync(0xffffffffu, a1, 2);
        unsigned long long f0 = __shfl_xor_sync(0xffffffffu, c0, 2);
        unsigned long long f1 = __shfl_xor_sync(0xffffffffu, c1, 2);

        unsigned long long acc[4] = {0ull, 0ull, 0ull, 0ull};
        #pragma unroll
        for (int dd=0; dd<4; dd++){
            fma2(acc[dd], a0, TT[dd][0].x);
            fma2(acc[dd], a1, TT[dd][0].y);
            fma2(acc[dd], c0, TT[dd][1].x);
            fma2(acc[dd], c1, TT[dd][1].y);
            fma2(acc[dd], e0, TT[dd][2].x);
            fma2(acc[dd], e1, TT[dd][2].y);
            fma2(acc[dd], f0, TT[dd][3].x);
            fma2(acc[dd], f1, TT[dd][3].y);
        }

        float4 colv = *reinterpret_cast<const float4*>(&shcol[jj*16 + q*4]);
        float4 rv = (kc==0) ? rv0 : (kc==1) ? rv1 : (kc==2) ? rv2 : rv3;
        float4 res;
        { float lo, hi; unpack2(acc[0], lo, hi); res.x = lo + hi; }
        { float lo, hi; unpack2(acc[1], lo, hi); res.y = lo + hi; }
        { float lo, hi; unpack2(acc[2], lo, hi); res.z = lo + hi; }
        { float lo, hi; unpack2(acc[3], lo, hi); res.w = lo + hi; }
        res.x += colv.x + rv.x;
        res.y += colv.y + rv.y;
        res.z += colv.z + rv.z;
        res.w += colv.w + rv.w;
        __stcs(orow + u*256 + t, res);

        wvA = wvB; wvB = wvC;
    }
}

// ---------------- launch ----------------
extern "C" void kernel_launch(void* const* d_in, const int* in_sizes, int n_in,
                              void* d_out, int out_size){
    (void)n_in; (void)out_size;
    const float* w[4]; const float* bb[4];
    int wi = 0, bi = 0;
    for (int i = 0; i < 8; i++){
        if (in_sizes[i] > 1000000) w[wi++] = (const float*)d_in[i];
        else                       bb[bi++] = (const float*)d_in[i];
    }
    const float* sw0 = (const float*)d_in[8];
    const float* sb0 = (const float*)d_in[9];
    const float* sw1 = (const float*)d_in[10];
    const float* sb1 = (const float*)d_in[11];
    const float* sw2 = (const float*)d_in[12];
    const float* sb2 = (const float*)d_in[13];
    const float* swo = (const float*)d_in[14];
    const float* sbo = (const float*)d_in[15];
    float* out = (float*)d_out;

    reduce_pass1<<<dim3(10, NB, NL), 256>>>(w[0], w[1], w[2], w[3],
                                            sw0, sb0, sw1, sb1, sw2, sb2, swo, sbo);
    reduce_pass2<<<64, 256>>>(bb[0], bb[1], bb[2], bb[3]);
    colrow_kernel<<<256, 256>>>(bb[0], bb[1], bb[2], bb[3], out);
    main_kernel<<<dim3(64, NB, NL), 256>>>(w[0], w[1], w[2], w[3],
                                           bb[0], bb[1], bb[2], bb[3], out);
}

// round 16
// speedup vs baseline: 1.4325x; 1.0765x over previous
#include <cuda_runtime.h>
#include <math.h>

#define NL 4
#define NB 16
#define NN 256
#define NC 16
#define NHID 64
#define INV256F (1.0f/256.0f)
#define INVNORM 0.06454972243679028f   /* 1/sqrt(240) */
#define OW_STRIDE 16842752             /* per-layer stride in d_out (ow + ob) */
#define OB_OFF    16777216             /* offset of ob within a layer chunk */

// ---------------- scratch (device globals; no allocs) ----------------
__device__ float g_terms[100*256];          // 100 siren points x (16c x 16d)
__device__ float g_rsums[NL*NB*NN*NC];      // mean over j  -> [l][b][k][c]
__device__ float g_csums[NL*NB*NN*NC];      // mean over k  -> [l][b][j][c]
__device__ float g_rpart[4*NL*NB*NN*NC];    // 4 j-quarter partial sums over j
__device__ float g_cpart[2*NL*NB*NN*NC];    // 2 k-half partial sums over k
__device__ float g_allsums[NB*NC*NL];       // [b][c][l]
__device__ float g_sumsb[NB*NC*NL];         // [b][c][l]
__device__ float g_basew[NL*NB*NC];         // [l][b][d]
__device__ float g_rowterm[NL*NB*NN*NC];    // [l][b][k][d]

// g_terms point layout:
// global: t*16 + a*4 + b   (t=0..3)
// diag:   64 + t*4 + i     (t=0..5)
// p1:     88 + t*3 + i     (t=0..1, i=0..2)
// m1:     94 + t*3 + i

__device__ __forceinline__ float f_li(int i){ return -1.0f + (2.0f/3.0f)*i; }
__device__ __forceinline__ float f_ti(int m){ return -1.0f + (2.0f/13.0f)*m; }

__device__ __forceinline__ unsigned long long pack2(float lo, float hi){
    unsigned long long r;
    asm("mov.b64 %0, {%1, %2};" : "=l"(r) : "f"(lo), "f"(hi));
    return r;
}
__device__ __forceinline__ void fma2(unsigned long long& d, unsigned long long a, unsigned long long b){
    asm("fma.rn.f32x2 %0, %1, %2, %0;" : "+l"(d) : "l"(a), "l"(b));
}
__device__ __forceinline__ void unpack2(unsigned long long v, float& lo, float& hi){
    asm("mov.b64 {%0, %1}, %2;" : "=f"(lo), "=f"(hi) : "l"(v));
}

#define CP_ASYNC16(saddr, gptr) \
    asm volatile("cp.async.cg.shared.global [%0], [%1], 16;" :: "r"(saddr), "l"(gptr))
#define CP_COMMIT() asm volatile("cp.async.commit_group;")
#define CP_WAIT(n)  asm volatile("cp.async.wait_group %0;" :: "n"(n))

// quad all-gather of a float4 (c-quarter) -> 4 slots of c-pairs
__device__ __forceinline__ void gather4(float4 v, unsigned long long g[4][2]){
    g[0][0] = pack2(v.x, v.y);
    g[0][1] = pack2(v.z, v.w);
    g[1][0] = __shfl_xor_sync(0xffffffffu, g[0][0], 1);
    g[1][1] = __shfl_xor_sync(0xffffffffu, g[0][1], 1);
    g[2][0] = __shfl_xor_sync(0xffffffffu, g[0][0], 2);
    g[2][1] = __shfl_xor_sync(0xffffffffu, g[0][1], 2);
    g[3][0] = __shfl_xor_sync(0xffffffffu, g[1][0], 2);
    g[3][1] = __shfl_xor_sync(0xffffffffu, g[1][1], 2);
}

// acc[dd] += (vector g) dot (matrix Tm rows for d-quarter q)
__device__ __forceinline__ void mat_acc(unsigned long long acc[4],
                                        const unsigned long long g[4][2],
                                        const unsigned long long* Tm, int q){
    #pragma unroll
    for (int dd=0; dd<4; dd++){
        const ulonglong2* row = reinterpret_cast<const ulonglong2*>(Tm + (q*4+dd)*8);
        #pragma unroll
        for (int s=0; s<4; s++){
            ulonglong2 tv = row[q^s];
            fma2(acc[dd], g[s][0], tv.x);
            fma2(acc[dd], g[s][1], tv.y);
        }
    }
}

// ---------------- SIREN body (called from reduce_pass1 extra blocks) ----------------
__device__ void siren_compute(int p, int t,
                              const float* __restrict__ sw0, const float* __restrict__ sb0,
                              const float* __restrict__ sw1, const float* __restrict__ sb1,
                              const float* __restrict__ sw2, const float* __restrict__ sb2,
                              const float* __restrict__ swo, const float* __restrict__ sbo){
    float x0, x1, x2;
    if (p < 64){        int tt=p>>4, a=(p>>2)&3, bb=p&3; x0=f_li(a);   x1=f_li(bb);  x2=f_ti(tt); }
    else if (p < 88){   int q=p-64;  int tt=q>>2, i=q&3; x0=f_li(i);   x1=f_li(i);   x2=f_ti(4+tt); }
    else if (p < 94){   int q=p-88;  int tt=q/3,  i=q%3; x0=f_li(i);   x1=f_li(i+1); x2=f_ti(10+tt); }
    else {              int q=p-94;  int tt=q/3,  i=q%3; x0=f_li(i+1); x1=f_li(i);   x2=f_ti(12+tt); }

    __shared__ float h[NHID];
    if (t < NHID){
        float v = x0*sw0[t] + x1*sw0[NHID+t] + x2*sw0[2*NHID+t] + sb0[t];
        h[t] = sinf(30.0f * v);
    }
    __syncthreads();

    if (t < NHID){
        float a1 = sb1[t];
        #pragma unroll 8
        for (int j=0;j<NHID;j++) a1 = fmaf(h[j], sw1[j*NHID+t], a1);
        a1 = sinf(a1);
        __syncthreads(); h[t] = a1;
    } else __syncthreads();
    __syncthreads();

    if (t < NHID){
        float a2 = sb2[t];
        #pragma unroll 8
        for (int j=0;j<NHID;j++) a2 = fmaf(h[j], sw2[j*NHID+t], a2);
        a2 = sinf(a2);
        __syncthreads(); h[t] = a2;
    } else __syncthreads();
    __syncthreads();

    {
        int o = t;
        float acc = sbo[o];
        #pragma unroll 8
        for (int j=0;j<NHID;j++) acc = fmaf(h[j], swo[j*256+o], acc);
        g_terms[p*256 + o] = acc * INVNORM;
    }
}

// ---------------- reduce pass 1 (+ siren blocks): csums/rsums partials ----------------
__global__ void __launch_bounds__(256, 2)
reduce_pass1(const float* __restrict__ w0, const float* __restrict__ w1,
             const float* __restrict__ w2, const float* __restrict__ w3,
             const float* __restrict__ sw0, const float* __restrict__ sb0,
             const float* __restrict__ sw1, const float* __restrict__ sb1,
             const float* __restrict__ sw2, const float* __restrict__ sb2,
             const float* __restrict__ swo, const float* __restrict__ sbo){
    int b  = blockIdx.y;
    int l  = blockIdx.z;
    if (blockIdx.x >= 8){
        int p = (blockIdx.x - 8)*64 + b*4 + l;
        if (p < 100) siren_compute(p, threadIdx.x, sw0, sb0, sw1, sb1, sw2, sb2, swo, sbo);
        return;
    }
    int jq = blockIdx.x & 3;
    int kh = blockIdx.x >> 2;
    const float* w = (l==0)?w0:(l==1)?w1:(l==2)?w2:w3;

    int t      = threadIdx.x;
    int c4     = t & 3;
    int klocal = t >> 2;
    int lane   = t & 31;
    int warp   = t >> 5;

    const float4* wp = reinterpret_cast<const float4*>(w);
    __shared__ float4 sh[8][16][4][4];   // [warp][jj][kgroup][c4]  32KB

    float4 racc[2];
    #pragma unroll
    for (int kc=0; kc<2; kc++) racc[kc] = make_float4(0.f,0.f,0.f,0.f);

    for (int sub=0; sub<4; sub++){
        int j0 = jq*64 + sub*16;
        float4 csum[16];
        #pragma unroll
        for (int jj=0; jj<16; jj++) csum[jj] = make_float4(0.f,0.f,0.f,0.f);

        #pragma unroll
        for (int kc=0; kc<2; kc++){
            int k = kh*128 + kc*64 + klocal;
            int base = ((b*NN + j0)*NN + k)*4 + c4;
            #pragma unroll
            for (int jj=0; jj<16; jj++){
                float4 v = __ldg(wp + base + jj*1024);
                racc[kc].x += v.x; racc[kc].y += v.y; racc[kc].z += v.z; racc[kc].w += v.w;
                csum[jj].x += v.x; csum[jj].y += v.y; csum[jj].z += v.z; csum[jj].w += v.w;
            }
        }

        #pragma unroll
        for (int jj=0; jj<16; jj++){
            float4 s = csum[jj];
            s.x += __shfl_xor_sync(0xffffffffu, s.x, 16);
            s.y += __shfl_xor_sync(0xffffffffu, s.y, 16);
            s.z += __shfl_xor_sync(0xffffffffu, s.z, 16);
            s.w += __shfl_xor_sync(0xffffffffu, s.w, 16);
            if (lane < 16) sh[warp][jj][lane >> 2][lane & 3] = s;
        }
        __syncthreads();

        if (t < 64){
            int jj = t >> 2, cc = t & 3;
            float4 s = make_float4(0.f,0.f,0.f,0.f);
            #pragma unroll
            for (int ww=0; ww<8; ww++){
                #pragma unroll
                for (int kg=0; kg<4; kg++){
                    float4 v = sh[ww][jj][kg][cc];
                    s.x += v.x; s.y += v.y; s.z += v.z; s.w += v.w;
                }
            }
            reinterpret_cast<float4*>(g_cpart)[(((kh*NL + l)*NB + b)*NN + j0 + jj)*4 + cc] = s;
        }
        __syncthreads();
    }

    #pragma unroll
    for (int kc=0; kc<2; kc++){
        int k = kh*128 + kc*64 + klocal;
        reinterpret_cast<float4*>(g_rpart)[(((jq*NL + l)*NB + b)*NN + k)*4 + c4] = racc[kc];
    }
}

// ---------------- reduce pass 2: rsums + csums (final) + allsums + sums_b ----------------
__global__ void reduce_pass2(const float* __restrict__ b0, const float* __restrict__ b1,
                             const float* __restrict__ b2, const float* __restrict__ b3){
    int l = blockIdx.x >> 4, b = blockIdx.x & 15;
    const float* bl = (l==0)?b0:(l==1)?b1:(l==2)?b2:b3;
    int k = threadIdx.x;
    int lane = k & 31, warp = k >> 5;
    __shared__ float4 sh2[8][4];
    __shared__ float4 sh3[8][4];

    float4 tot[4];
    #pragma unroll
    for (int c4=0; c4<4; c4++){
        float4 s = make_float4(0.f,0.f,0.f,0.f);
        #pragma unroll
        for (int jq=0; jq<4; jq++){
            float4 v = __ldg(reinterpret_cast<const float4*>(g_rpart) +
                             ((((jq*NL + l)*NB + b)*NN + k)*4 + c4));
            s.x += v.x; s.y += v.y; s.z += v.z; s.w += v.w;
        }
        s.x *= INV256F; s.y *= INV256F; s.z *= INV256F; s.w *= INV256F;
        reinterpret_cast<float4*>(g_rsums)[((l*NB + b)*NN + k)*4 + c4] = s;
        tot[c4] = s;
    }

    {
        const float4* c0 = reinterpret_cast<const float4*>(g_cpart) + ((0*NL + l)*NB + b)*1024;
        const float4* c1 = reinterpret_cast<const float4*>(g_cpart) + ((1*NL + l)*NB + b)*1024;
        float4* cd = reinterpret_cast<float4*>(g_csums) + ((l*NB + b))*1024;
        #pragma unroll
        for (int i=0; i<4; i++){
            int u = i*256 + k;
            float4 a = __ldg(c0 + u), c = __ldg(c1 + u);
            float4 r;
            r.x = (a.x + c.x) * INV256F;
            r.y = (a.y + c.y) * INV256F;
            r.z = (a.z + c.z) * INV256F;
            r.w = (a.w + c.w) * INV256F;
            cd[u] = r;
        }
    }

    #pragma unroll
    for (int c4=0; c4<4; c4++){
        float4 s = tot[c4];
        #pragma unroll
        for (int m=1; m<32; m<<=1){
            s.x += __shfl_xor_sync(0xffffffffu, s.x, m);
            s.y += __shfl_xor_sync(0xffffffffu, s.y, m);
            s.z += __shfl_xor_sync(0xffffffffu, s.z, m);
            s.w += __shfl_xor_sync(0xffffffffu, s.w, m);
        }
        if (lane == 0) sh2[warp][c4] = s;
    }

    {
        const float4* bp = reinterpret_cast<const float4*>(bl) + b*1024;
        float4 s = make_float4(0.f,0.f,0.f,0.f);
        #pragma unroll
        for (int i=0; i<4; i++){
            float4 v = __ldg(bp + i*256 + k);
            s.x += v.x; s.y += v.y; s.z += v.z; s.w += v.w;
        }
        #pragma unroll
        for (int m=4; m<32; m<<=1){
            s.x += __shfl_xor_sync(0xffffffffu, s.x, m);
            s.y += __shfl_xor_sync(0xffffffffu, s.y, m);
            s.z += __shfl_xor_sync(0xffffffffu, s.z, m);
            s.w += __shfl_xor_sync(0xffffffffu, s.w, m);
        }
        if (lane < 4) sh3[warp][lane] = s;
    }
    __syncthreads();

    if (k < 4){
        float4 s = make_float4(0.f,0.f,0.f,0.f);
        #pragma unroll
        for (int ww=0; ww<8; ww++){
            float4 v = sh2[ww][k];
            s.x += v.x; s.y += v.y; s.z += v.z; s.w += v.w;
        }
        int cb = k*4;
        g_allsums[b*64 + (cb+0)*4 + l] = s.x * INV256F;
        g_allsums[b*64 + (cb+1)*4 + l] = s.y * INV256F;
        g_allsums[b*64 + (cb+2)*4 + l] = s.z * INV256F;
        g_allsums[b*64 + (cb+3)*4 + l] = s.w * INV256F;
    } else if (k >= 8 && k < 12){
        int c4 = k - 8;
        float4 s = make_float4(0.f,0.f,0.f,0.f);
        #pragma unroll
        for (int ww=0; ww<8; ww++){
            float4 v = sh3[ww][c4];
            s.x += v.x; s.y += v.y; s.z += v.z; s.w += v.w;
        }
        int cb = c4*4;
        g_sumsb[b*64 + (cb+0)*4 + l] = s.x * INV256F;
        g_sumsb[b*64 + (cb+1)*4 + l] = s.y * INV256F;
        g_sumsb[b*64 + (cb+2)*4 + l] = s.z * INV256F;
        g_sumsb[b*64 + (cb+3)*4 + l] = s.w * INV256F;
    }
}

// ---------------- colrow: rowterm + ob (+ basew for main) ----------------
__global__ void __launch_bounds__(256, 2)
colrow_kernel(const float* __restrict__ b0, const float* __restrict__ b1,
              const float* __restrict__ b2, const float* __restrict__ b3,
              float* __restrict__ out){
    int rem = blockIdx.x;
    int l = rem >> 6, b = (rem >> 2) & 15, xt = rem & 3;
    int t = threadIdx.x, q = t & 3;
    int x = xt*64 + (t >> 2);

    __shared__ unsigned long long Tt[6*128];
    __shared__ float sh_base[16];

    int terms[6];
    terms[0] = 64 + l; terms[1] = 76 + l;      // rowterm: wrow(v0=rs), w_b(v1=bv)
    terms[2] = 80 + l; terms[3] = 84 + l;      // ob: b_wcol(v0=rs), bb(v1=bv)
    int nm = 4;
    if (l < 3){ terms[4] = 88 + l; terms[5] = 91 + l; nm = 6; }
    if (t < 128){
        int d = t >> 3, c2 = t & 7;
        for (int m=0; m<nm; m++){
            float lo = __ldg(&g_terms[terms[m]*256 + (2*c2  )*16 + d]);
            float hi = __ldg(&g_terms[terms[m]*256 + (2*c2+1)*16 + d]);
            Tt[m*128 + t] = pack2(lo, hi);
        }
    } else if (t >= 208 && t < 240){
        int wb = (t >= 224);
        int d = t - (wb ? 224 : 208);
        int off = wb ? 32 : 0;
        float acc = 0.f;
        #pragma unroll
        for (int lp=0; lp<NL; lp++){
            #pragma unroll
            for (int c=0; c<NC; c++){
                float as  = g_allsums[b*64 + c*4 + lp];
                float sbv = g_sumsb[b*64 + c*4 + lp];
                int e = c*16 + d;
                acc = fmaf(as,  g_terms[(off      + l*4 + lp)*256 + e], acc);
                acc = fmaf(sbv, g_terms[(off + 16 + l*4 + lp)*256 + e], acc);
            }
        }
        if (wb) sh_base[d] = acc;
        else    g_basew[(l*NB + b)*NC + d] = acc;
    }
    __syncthreads();

    const float4* csp = reinterpret_cast<const float4*>(g_csums);
    const float4* rsp = reinterpret_cast<const float4*>(g_rsums);
    float4 basev = *reinterpret_cast<const float4*>(&sh_base[q*4]);

    const float* blp = (l==0)?b0:(l==1)?b1:(l==2)?b2:b3;
    float4 v0 = __ldg(rsp + ((l*NB + b)*NN + x)*4 + q);
    float4 v1 = __ldg(reinterpret_cast<const float4*>(blp) + (b*NN + x)*4 + q);
    unsigned long long g0[4][2], g1[4][2];
    gather4(v0, g0);
    gather4(v1, g1);

    unsigned long long accA[4] = {0ull,0ull,0ull,0ull};   // rowterm
    unsigned long long accB[4] = {0ull,0ull,0ull,0ull};   // ob
    mat_acc(accA, g0, &Tt[0],   q);
    mat_acc(accA, g1, &Tt[128], q);
    mat_acc(accB, g0, &Tt[256], q);
    mat_acc(accB, g1, &Tt[384], q);
    if (l < 3){
        float4 v2 = __ldg(csp + (((l+1)*NB + b)*NN + x)*4 + q);
        unsigned long long g2[4][2];
        gather4(v2, g2);
        mat_acc(accA, g2, &Tt[512], q);
        mat_acc(accB, g2, &Tt[640], q);
    }

    float4 resA;
    { float lo, hi; unpack2(accA[0], lo, hi); resA.x = lo + hi; }
    { float lo, hi; unpack2(accA[1], lo, hi); resA.y = lo + hi; }
    { float lo, hi; unpack2(accA[2], lo, hi); resA.z = lo + hi; }
    { float lo, hi; unpack2(accA[3], lo, hi); resA.w = lo + hi; }
    reinterpret_cast<float4*>(g_rowterm)[((l*NB + b)*NN + x)*4 + q] = resA;

    float4 resB;
    { float lo, hi; unpack2(accB[0], lo, hi); resB.x = lo + hi + basev.x; }
    { float lo, hi; unpack2(accB[1], lo, hi); resB.y = lo + hi + basev.y; }
    { float lo, hi; unpack2(accB[2], lo, hi); resB.z = lo + hi + basev.z; }
    { float lo, hi; unpack2(accB[3], lo, hi); resB.w = lo + hi + basev.w; }
    reinterpret_cast<float4*>(out + (size_t)l*OW_STRIDE + OB_OFF)[(b*NN + x)*4 + q] = resB;
}

// ---------------- main output pass: 4 j-rows per block, cp.async 6-stage w ring ----------------
// grid (64, 16, 4), 256 threads. w streamed via cp.async.cg (prefetch distance 5);
// each thread reads ONLY its own 16B slot -> per-thread wait_group, no barrier in loop.
__global__ void __launch_bounds__(256, 2)
main_kernel(const float* __restrict__ w0, const float* __restrict__ w1,
            const float* __restrict__ w2, const float* __restrict__ w3,
            const float* __restrict__ b0, const float* __restrict__ b1,
            const float* __restrict__ b2, const float* __restrict__ b3,
            float* __restrict__ out){
    int l  = 3 - (int)blockIdx.z;
    int b  = 15 - (int)blockIdx.y;
    int jx = 63 - (int)blockIdx.x;
    int j0 = jx*4;
    int t = threadIdx.x;
    int q = t & 3;
    const float* w = (l==0)?w0:(l==1)?w1:(l==2)?w2:w3;

    const float4* wrow = reinterpret_cast<const float4*>(w) + (size_t)(b*NN + j0)*1024;
    const float4* rrow = reinterpret_cast<const float4*>(g_rowterm) + (size_t)(l*NB + b)*1024;
    float4*       orow = reinterpret_cast<float4*>(out + (size_t)l*OW_STRIDE) + (size_t)(b*NN + j0)*1024;

    __shared__ float4 wbuf[6][256];            // 24KB w ring
    __shared__ unsigned long long Tt_s[128];   // [d][c2] c-paired transposed T
    __shared__ float shcol[64];                // colterm rows j0..j0+3

    unsigned wb_base;
    asm("{ .reg .u64 tmp; cvta.to.shared.u64 tmp, %1; cvt.u32.u64 %0, tmp; }"
        : "=r"(wb_base) : "l"(wbuf));
    unsigned my_off = (unsigned)(t*16);

    // issue stages 0..4 (5 groups in flight)
    #pragma unroll
    for (int s=0; s<5; s++){
        CP_ASYNC16(wb_base + (unsigned)(s*4096) + my_off, wrow + s*256 + t);
        CP_COMMIT();
    }

    // rowterm (reused across all 4 j) — register resident
    float4 rv0 = __ldg(rrow + 0*256 + t);
    float4 rv1 = __ldg(rrow + 1*256 + t);
    float4 rv2 = __ldg(rrow + 2*256 + t);
    float4 rv3 = __ldg(rrow + 3*256 + t);

    if (t < 128){
        int d = t >> 3, c2 = t & 7;
        float lo = __ldg(&g_terms[(72+l)*256 + (2*c2  )*16 + d]);
        float hi = __ldg(&g_terms[(72+l)*256 + (2*c2+1)*16 + d]);
        Tt_s[t] = pack2(lo, hi);
    } else if (t >= 192){
        int r = t - 192;                // 0..63
        int jj = r >> 4, d = r & 15;
        int j = j0 + jj;
        float acc = __ldg(&g_basew[(l*NB + b)*NC + d]);
        const float* cs = &g_csums[((l*NB + b)*NN + j)*NC];
        const float* T1 = &g_terms[(68 + l)*256];          // t_w_wcol
        #pragma unroll
        for (int c=0; c<NC; c++) acc = fmaf(cs[c], T1[c*16 + d], acc);
        if (l > 0){
            const float* rs  = &g_rsums[(((l-1)*NB + b)*NN + j)*NC];
            const float* bp  = ((l-1)==0?b0:(l-1)==1?b1:(l-1)==2?b2:b3) + (b*NN + j)*NC;
            const float* Tm0 = &g_terms[(94 + (l-1))*256]; // t_w_wm1
            const float* Tm1 = &g_terms[(97 + (l-1))*256]; // t_w_bm1
            #pragma unroll
            for (int c=0; c<NC; c++){
                acc = fmaf(rs[c], Tm0[c*16 + d], acc);
                acc = fmaf(bp[c], Tm1[c*16 + d], acc);
            }
        }
        shcol[r] = acc;
    }
    __syncthreads();

    int q1 = q^1, q2 = q^2, q3 = q^3;
    ulonglong2 TT[4][4];
    #pragma unroll
    for (int dd=0; dd<4; dd++){
        const ulonglong2* row = reinterpret_cast<const ulonglong2*>(&Tt_s[(q*4+dd)*8]);
        TT[dd][0] = row[q];
        TT[dd][1] = row[q1];
        TT[dd][2] = row[q2];
        TT[dd][3] = row[q3];
    }

    #pragma unroll
    for (int u=0; u<16; u++){
        int kc = u & 3;
        int jj = u >> 2;

        if (u + 5 < 16){
            int s = u + 5;
            CP_ASYNC16(wb_base + (unsigned)((s % 6)*4096) + my_off, wrow + s*256 + t);
            CP_COMMIT();
        }
        // ensure stage u is complete (pending allowed = min(5, 15-u))
        if      (u < 11) CP_WAIT(5);
        else if (u == 11) CP_WAIT(4);
        else if (u == 12) CP_WAIT(3);
        else if (u == 13) CP_WAIT(2);
        else if (u == 14) CP_WAIT(1);
        else              CP_WAIT(0);

        float4 wv = wbuf[u % 6][t];

        unsigned long long a0 = pack2(wv.x, wv.y);
        unsigned long long a1 = pack2(wv.z, wv.w);
        unsigned long long c0 = __shfl_xor_sync(0xffffffffu, a0, 1);
        unsigned long long c1 = __shfl_xor_sync(0xffffffffu, a1, 1);
        unsigned long long e0 = __shfl_xor_sync(0xffffffffu, a0, 2);
        unsigned long long e1 = __shfl_xor_sync(0xffffffffu, a1, 2);
        unsigned long long f0 = __shfl_xor_sync(0xffffffffu, c0, 2);
        unsigned long long f1 = __shfl_xor_sync(0xffffffffu, c1, 2);

        unsigned long long acc[4] = {0ull, 0ull, 0ull, 0ull};
        #pragma unroll
        for (int dd=0; dd<4; dd++){
            fma2(acc[dd], a0, TT[dd][0].x);
            fma2(acc[dd], a1, TT[dd][0].y);
            fma2(acc[dd], c0, TT[dd][1].x);
            fma2(acc[dd], c1, TT[dd][1].y);
            fma2(acc[dd], e0, TT[dd][2].x);
            fma2(acc[dd], e1, TT[dd][2].y);
            fma2(acc[dd], f0, TT[dd][3].x);
            fma2(acc[dd], f1, TT[dd][3].y);
        }

        float4 colv = *reinterpret_cast<const float4*>(&shcol[jj*16 + q*4]);
        float4 rv = (kc==0) ? rv0 : (kc==1) ? rv1 : (kc==2) ? rv2 : rv3;
        float4 res;
        { float lo, hi; unpack2(acc[0], lo, hi); res.x = lo + hi; }
        { float lo, hi; unpack2(acc[1], lo, hi); res.y = lo + hi; }
        { float lo, hi; unpack2(acc[2], lo, hi); res.z = lo + hi; }
        { float lo, hi; unpack2(acc[3], lo, hi); res.w = lo + hi; }
        res.x += colv.x + rv.x;
        res.y += colv.y + rv.y;
        res.z += colv.z + rv.z;
        res.w += colv.w + rv.w;
        orow[u*256 + t] = res;
    }
}

// ---------------- launch ----------------
extern "C" void kernel_launch(void* const* d_in, const int* in_sizes, int n_in,
                              void* d_out, int out_size){
    (void)n_in; (void)out_size;
    const float* w[4]; const float* bb[4];
    int wi = 0, bi = 0;
    for (int i = 0; i < 8; i++){
        if (in_sizes[i] > 1000000) w[wi++] = (const float*)d_in[i];
        else                       bb[bi++] = (const float*)d_in[i];
    }
    const float* sw0 = (const float*)d_in[8];
    const float* sb0 = (const float*)d_in[9];
    const float* sw1 = (const float*)d_in[10];
    const float* sb1 = (const float*)d_in[11];
    const float* sw2 = (const float*)d_in[12];
    const float* sb2 = (const float*)d_in[13];
    const float* swo = (const float*)d_in[14];
    const float* sbo = (const float*)d_in[15];
    float* out = (float*)d_out;

    reduce_pass1<<<dim3(10, NB, NL), 256>>>(w[0], w[1], w[2], w[3],
                                            sw0, sb0, sw1, sb1, sw2, sb2, swo, sbo);
    reduce_pass2<<<64, 256>>>(bb[0], bb[1], bb[2], bb[3]);
    colrow_kernel<<<256, 256>>>(bb[0], bb[1], bb[2], bb[3], out);
    main_kernel<<<dim3(64, NB, NL), 256>>>(w[0], w[1], w[2], w[3],
                                           bb[0], bb[1], bb[2], bb[3], out);
}

// round 17
// speedup vs baseline: 1.4474x; 1.0104x over previous
#include <cuda_runtime.h>
#include <math.h>

#define NL 4
#define NB 16
#define NN 256
#define NC 16
#define NHID 64
#define INV256F (1.0f/256.0f)
#define INVNORM 0.06454972243679028f   /* 1/sqrt(240) */
#define OW_STRIDE 16842752             /* per-layer stride in d_out (ow + ob) */
#define OB_OFF    16777216             /* offset of ob within a layer chunk */

// ---------------- scratch (device globals; no allocs) ----------------
__device__ float g_terms[100*256];          // 100 siren points x (16c x 16d)
__device__ float g_rsums[NL*NB*NN*NC];      // mean over j  -> [l][b][k][c]
__device__ float g_csums[NL*NB*NN*NC];      // mean over k  -> [l][b][j][c]
__device__ float g_rpart[4*NL*NB*NN*NC];    // 4 j-quarter partial sums over j
__device__ float g_cpart[2*NL*NB*NN*NC];    // 2 k-half partial sums over k
__device__ float g_allsums[NB*NC*NL];       // [b][c][l]
__device__ float g_sumsb[NB*NC*NL];         // [b][c][l]
__device__ float g_basew[NL*NB*NC];         // [l][b][d]
__device__ float g_rowterm[NL*NB*NN*NC];    // [l][b][k][d]

// g_terms point layout:
// global: t*16 + a*4 + b   (t=0..3)
// diag:   64 + t*4 + i     (t=0..5)
// p1:     88 + t*3 + i     (t=0..1, i=0..2)
// m1:     94 + t*3 + i

__device__ __forceinline__ float f_li(int i){ return -1.0f + (2.0f/3.0f)*i; }
__device__ __forceinline__ float f_ti(int m){ return -1.0f + (2.0f/13.0f)*m; }

__device__ __forceinline__ unsigned long long pack2(float lo, float hi){
    unsigned long long r;
    asm("mov.b64 %0, {%1, %2};" : "=l"(r) : "f"(lo), "f"(hi));
    return r;
}
__device__ __forceinline__ void fma2(unsigned long long& d, unsigned long long a, unsigned long long b){
    asm("fma.rn.f32x2 %0, %1, %2, %0;" : "+l"(d) : "l"(a), "l"(b));
}
__device__ __forceinline__ void unpack2(unsigned long long v, float& lo, float& hi){
    asm("mov.b64 {%0, %1}, %2;" : "=f"(lo), "=f"(hi) : "l"(v));
}

#define CP_ASYNC16(saddr, gptr) \
    asm volatile("cp.async.cg.shared.global [%0], [%1], 16;" :: "r"(saddr), "l"(gptr))
#define CP_COMMIT() asm volatile("cp.async.commit_group;")
#define CP_WAIT(n)  asm volatile("cp.async.wait_group %0;" :: "n"(n))

// quad all-gather of a float4 (c-quarter) -> 4 slots of c-pairs
__device__ __forceinline__ void gather4(float4 v, unsigned long long g[4][2]){
    g[0][0] = pack2(v.x, v.y);
    g[0][1] = pack2(v.z, v.w);
    g[1][0] = __shfl_xor_sync(0xffffffffu, g[0][0], 1);
    g[1][1] = __shfl_xor_sync(0xffffffffu, g[0][1], 1);
    g[2][0] = __shfl_xor_sync(0xffffffffu, g[0][0], 2);
    g[2][1] = __shfl_xor_sync(0xffffffffu, g[0][1], 2);
    g[3][0] = __shfl_xor_sync(0xffffffffu, g[1][0], 2);
    g[3][1] = __shfl_xor_sync(0xffffffffu, g[1][1], 2);
}

// acc[dd] += (vector g) dot (matrix Tm rows for d-quarter q)
__device__ __forceinline__ void mat_acc(unsigned long long acc[4],
                                        const unsigned long long g[4][2],
                                        const unsigned long long* Tm, int q){
    #pragma unroll
    for (int dd=0; dd<4; dd++){
        const ulonglong2* row = reinterpret_cast<const ulonglong2*>(Tm + (q*4+dd)*8);
        #pragma unroll
        for (int s=0; s<4; s++){
            ulonglong2 tv = row[q^s];
            fma2(acc[dd], g[s][0], tv.x);
            fma2(acc[dd], g[s][1], tv.y);
        }
    }
}

// ---------------- SIREN body (called from reduce_pass1 extra blocks) ----------------
__device__ void siren_compute(int p, int t,
                              const float* __restrict__ sw0, const float* __restrict__ sb0,
                              const float* __restrict__ sw1, const float* __restrict__ sb1,
                              const float* __restrict__ sw2, const float* __restrict__ sb2,
                              const float* __restrict__ swo, const float* __restrict__ sbo){
    float x0, x1, x2;
    if (p < 64){        int tt=p>>4, a=(p>>2)&3, bb=p&3; x0=f_li(a);   x1=f_li(bb);  x2=f_ti(tt); }
    else if (p < 88){   int q=p-64;  int tt=q>>2, i=q&3; x0=f_li(i);   x1=f_li(i);   x2=f_ti(4+tt); }
    else if (p < 94){   int q=p-88;  int tt=q/3,  i=q%3; x0=f_li(i);   x1=f_li(i+1); x2=f_ti(10+tt); }
    else {              int q=p-94;  int tt=q/3,  i=q%3; x0=f_li(i+1); x1=f_li(i);   x2=f_ti(12+tt); }

    __shared__ float h[NHID];
    if (t < NHID){
        float v = x0*sw0[t] + x1*sw0[NHID+t] + x2*sw0[2*NHID+t] + sb0[t];
        h[t] = sinf(30.0f * v);
    }
    __syncthreads();

    if (t < NHID){
        float a1 = sb1[t];
        #pragma unroll 8
        for (int j=0;j<NHID;j++) a1 = fmaf(h[j], sw1[j*NHID+t], a1);
        a1 = sinf(a1);
        __syncthreads(); h[t] = a1;
    } else __syncthreads();
    __syncthreads();

    if (t < NHID){
        float a2 = sb2[t];
        #pragma unroll 8
        for (int j=0;j<NHID;j++) a2 = fmaf(h[j], sw2[j*NHID+t], a2);
        a2 = sinf(a2);
        __syncthreads(); h[t] = a2;
    } else __syncthreads();
    __syncthreads();

    {
        int o = t;
        float acc = sbo[o];
        #pragma unroll 8
        for (int j=0;j<NHID;j++) acc = fmaf(h[j], swo[j*256+o], acc);
        g_terms[p*256 + o] = acc * INVNORM;
    }
}

// ---------------- reduce pass 1 (+ siren blocks): csums/rsums partials ----------------
__global__ void __launch_bounds__(256, 2)
reduce_pass1(const float* __restrict__ w0, const float* __restrict__ w1,
             const float* __restrict__ w2, const float* __restrict__ w3,
             const float* __restrict__ sw0, const float* __restrict__ sb0,
             const float* __restrict__ sw1, const float* __restrict__ sb1,
             const float* __restrict__ sw2, const float* __restrict__ sb2,
             const float* __restrict__ swo, const float* __restrict__ sbo){
    int b  = blockIdx.y;
    int l  = blockIdx.z;
    if (blockIdx.x >= 8){
        int p = (blockIdx.x - 8)*64 + b*4 + l;
        if (p < 100) siren_compute(p, threadIdx.x, sw0, sb0, sw1, sb1, sw2, sb2, swo, sbo);
        return;
    }
    int jq = blockIdx.x & 3;
    int kh = blockIdx.x >> 2;
    const float* w = (l==0)?w0:(l==1)?w1:(l==2)?w2:w3;

    int t      = threadIdx.x;
    int c4     = t & 3;
    int klocal = t >> 2;
    int lane   = t & 31;
    int warp   = t >> 5;

    const float4* wp = reinterpret_cast<const float4*>(w);
    __shared__ float4 sh[8][16][4][4];   // [warp][jj][kgroup][c4]  32KB

    float4 racc[2];
    #pragma unroll
    for (int kc=0; kc<2; kc++) racc[kc] = make_float4(0.f,0.f,0.f,0.f);

    for (int sub=0; sub<4; sub++){
        int j0 = jq*64 + sub*16;
        float4 csum[16];
        #pragma unroll
        for (int jj=0; jj<16; jj++) csum[jj] = make_float4(0.f,0.f,0.f,0.f);

        #pragma unroll
        for (int kc=0; kc<2; kc++){
            int k = kh*128 + kc*64 + klocal;
            int base = ((b*NN + j0)*NN + k)*4 + c4;
            #pragma unroll
            for (int jj=0; jj<16; jj++){
                float4 v = __ldg(wp + base + jj*1024);
                racc[kc].x += v.x; racc[kc].y += v.y; racc[kc].z += v.z; racc[kc].w += v.w;
                csum[jj].x += v.x; csum[jj].y += v.y; csum[jj].z += v.z; csum[jj].w += v.w;
            }
        }

        #pragma unroll
        for (int jj=0; jj<16; jj++){
            float4 s = csum[jj];
            s.x += __shfl_xor_sync(0xffffffffu, s.x, 16);
            s.y += __shfl_xor_sync(0xffffffffu, s.y, 16);
            s.z += __shfl_xor_sync(0xffffffffu, s.z, 16);
            s.w += __shfl_xor_sync(0xffffffffu, s.w, 16);
            if (lane < 16) sh[warp][jj][lane >> 2][lane & 3] = s;
        }
        __syncthreads();

        if (t < 64){
            int jj = t >> 2, cc = t & 3;
            float4 s = make_float4(0.f,0.f,0.f,0.f);
            #pragma unroll
            for (int ww=0; ww<8; ww++){
                #pragma unroll
                for (int kg=0; kg<4; kg++){
                    float4 v = sh[ww][jj][kg][cc];
                    s.x += v.x; s.y += v.y; s.z += v.z; s.w += v.w;
                }
            }
            reinterpret_cast<float4*>(g_cpart)[(((kh*NL + l)*NB + b)*NN + j0 + jj)*4 + cc] = s;
        }
        __syncthreads();
    }

    #pragma unroll
    for (int kc=0; kc<2; kc++){
        int k = kh*128 + kc*64 + klocal;
        reinterpret_cast<float4*>(g_rpart)[(((jq*NL + l)*NB + b)*NN + k)*4 + c4] = racc[kc];
    }
}

// ---------------- reduce pass 2: rsums + csums (final) + allsums + sums_b ----------------
__global__ void reduce_pass2(const float* __restrict__ b0, const float* __restrict__ b1,
                             const float* __restrict__ b2, const float* __restrict__ b3){
    int l = blockIdx.x >> 4, b = blockIdx.x & 15;
    const float* bl = (l==0)?b0:(l==1)?b1:(l==2)?b2:b3;
    int k = threadIdx.x;
    int lane = k & 31, warp = k >> 5;
    __shared__ float4 sh2[8][4];
    __shared__ float4 sh3[8][4];

    float4 tot[4];
    #pragma unroll
    for (int c4=0; c4<4; c4++){
        float4 s = make_float4(0.f,0.f,0.f,0.f);
        #pragma unroll
        for (int jq=0; jq<4; jq++){
            float4 v = __ldg(reinterpret_cast<const float4*>(g_rpart) +
                             ((((jq*NL + l)*NB + b)*NN + k)*4 + c4));
            s.x += v.x; s.y += v.y; s.z += v.z; s.w += v.w;
        }
        s.x *= INV256F; s.y *= INV256F; s.z *= INV256F; s.w *= INV256F;
        reinterpret_cast<float4*>(g_rsums)[((l*NB + b)*NN + k)*4 + c4] = s;
        tot[c4] = s;
    }

    {
        const float4* c0 = reinterpret_cast<const float4*>(g_cpart) + ((0*NL + l)*NB + b)*1024;
        const float4* c1 = reinterpret_cast<const float4*>(g_cpart) + ((1*NL + l)*NB + b)*1024;
        float4* cd = reinterpret_cast<float4*>(g_csums) + ((l*NB + b))*1024;
        #pragma unroll
        for (int i=0; i<4; i++){
            int u = i*256 + k;
            float4 a = __ldg(c0 + u), c = __ldg(c1 + u);
            float4 r;
            r.x = (a.x + c.x) * INV256F;
            r.y = (a.y + c.y) * INV256F;
            r.z = (a.z + c.z) * INV256F;
            r.w = (a.w + c.w) * INV256F;
            cd[u] = r;
        }
    }

    #pragma unroll
    for (int c4=0; c4<4; c4++){
        float4 s = tot[c4];
        #pragma unroll
        for (int m=1; m<32; m<<=1){
            s.x += __shfl_xor_sync(0xffffffffu, s.x, m);
            s.y += __shfl_xor_sync(0xffffffffu, s.y, m);
            s.z += __shfl_xor_sync(0xffffffffu, s.z, m);
            s.w += __shfl_xor_sync(0xffffffffu, s.w, m);
        }
        if (lane == 0) sh2[warp][c4] = s;
    }

    {
        const float4* bp = reinterpret_cast<const float4*>(bl) + b*1024;
        float4 s = make_float4(0.f,0.f,0.f,0.f);
        #pragma unroll
        for (int i=0; i<4; i++){
            float4 v = __ldg(bp + i*256 + k);
            s.x += v.x; s.y += v.y; s.z += v.z; s.w += v.w;
        }
        #pragma unroll
        for (int m=4; m<32; m<<=1){
            s.x += __shfl_xor_sync(0xffffffffu, s.x, m);
            s.y += __shfl_xor_sync(0xffffffffu, s.y, m);
            s.z += __shfl_xor_sync(0xffffffffu, s.z, m);
            s.w += __shfl_xor_sync(0xffffffffu, s.w, m);
        }
        if (lane < 4) sh3[warp][lane] = s;
    }
    __syncthreads();

    if (k < 4){
        float4 s = make_float4(0.f,0.f,0.f,0.f);
        #pragma unroll
        for (int ww=0; ww<8; ww++){
            float4 v = sh2[ww][k];
            s.x += v.x; s.y += v.y; s.z += v.z; s.w += v.w;
        }
        int cb = k*4;
        g_allsums[b*64 + (cb+0)*4 + l] = s.x * INV256F;
        g_allsums[b*64 + (cb+1)*4 + l] = s.y * INV256F;
        g_allsums[b*64 + (cb+2)*4 + l] = s.z * INV256F;
        g_allsums[b*64 + (cb+3)*4 + l] = s.w * INV256F;
    } else if (k >= 8 && k < 12){
        int c4 = k - 8;
        float4 s = make_float4(0.f,0.f,0.f,0.f);
        #pragma unroll
        for (int ww=0; ww<8; ww++){
            float4 v = sh3[ww][c4];
            s.x += v.x; s.y += v.y; s.z += v.z; s.w += v.w;
        }
        int cb = c4*4;
        g_sumsb[b*64 + (cb+0)*4 + l] = s.x * INV256F;
        g_sumsb[b*64 + (cb+1)*4 + l] = s.y * INV256F;
        g_sumsb[b*64 + (cb+2)*4 + l] = s.z * INV256F;
        g_sumsb[b*64 + (cb+3)*4 + l] = s.w * INV256F;
    }
}

// ---------------- colrow: rowterm + ob (+ basew for main) ----------------
__global__ void __launch_bounds__(256, 2)
colrow_kernel(const float* __restrict__ b0, const float* __restrict__ b1,
              const float* __restrict__ b2, const float* __restrict__ b3,
              float* __restrict__ out){
    int rem = blockIdx.x;
    int l = rem >> 6, b = (rem >> 2) & 15, xt = rem & 3;
    int t = threadIdx.x, q = t & 3;
    int x = xt*64 + (t >> 2);

    __shared__ unsigned long long Tt[6*128];
    __shared__ float sh_base[16];

    int terms[6];
    terms[0] = 64 + l; terms[1] = 76 + l;      // rowterm: wrow(v0=rs), w_b(v1=bv)
    terms[2] = 80 + l; terms[3] = 84 + l;      // ob: b_wcol(v0=rs), bb(v1=bv)
    int nm = 4;
    if (l < 3){ terms[4] = 88 + l; terms[5] = 91 + l; nm = 6; }
    if (t < 128){
        int d = t >> 3, c2 = t & 7;
        for (int m=0; m<nm; m++){
            float lo = __ldg(&g_terms[terms[m]*256 + (2*c2  )*16 + d]);
            float hi = __ldg(&g_terms[terms[m]*256 + (2*c2+1)*16 + d]);
            Tt[m*128 + t] = pack2(lo, hi);
        }
    } else if (t >= 208 && t < 240){
        int wb = (t >= 224);
        int d = t - (wb ? 224 : 208);
        int off = wb ? 32 : 0;
        float acc = 0.f;
        #pragma unroll
        for (int lp=0; lp<NL; lp++){
            #pragma unroll
            for (int c=0; c<NC; c++){
                float as  = g_allsums[b*64 + c*4 + lp];
                float sbv = g_sumsb[b*64 + c*4 + lp];
                int e = c*16 + d;
                acc = fmaf(as,  g_terms[(off      + l*4 + lp)*256 + e], acc);
                acc = fmaf(sbv, g_terms[(off + 16 + l*4 + lp)*256 + e], acc);
            }
        }
        if (wb) sh_base[d] = acc;
        else    g_basew[(l*NB + b)*NC + d] = acc;
    }
    __syncthreads();

    const float4* csp = reinterpret_cast<const float4*>(g_csums);
    const float4* rsp = reinterpret_cast<const float4*>(g_rsums);
    float4 basev = *reinterpret_cast<const float4*>(&sh_base[q*4]);

    const float* blp = (l==0)?b0:(l==1)?b1:(l==2)?b2:b3;
    float4 v0 = __ldg(rsp + ((l*NB + b)*NN + x)*4 + q);
    float4 v1 = __ldg(reinterpret_cast<const float4*>(blp) + (b*NN + x)*4 + q);
    unsigned long long g0[4][2], g1[4][2];
    gather4(v0, g0);
    gather4(v1, g1);

    unsigned long long accA[4] = {0ull,0ull,0ull,0ull};   // rowterm
    unsigned long long accB[4] = {0ull,0ull,0ull,0ull};   // ob
    mat_acc(accA, g0, &Tt[0],   q);
    mat_acc(accA, g1, &Tt[128], q);
    mat_acc(accB, g0, &Tt[256], q);
    mat_acc(accB, g1, &Tt[384], q);
    if (l < 3){
        float4 v2 = __ldg(csp + (((l+1)*NB + b)*NN + x)*4 + q);
        unsigned long long g2[4][2];
        gather4(v2, g2);
        mat_acc(accA, g2, &Tt[512], q);
        mat_acc(accB, g2, &Tt[640], q);
    }

    float4 resA;
    { float lo, hi; unpack2(accA[0], lo, hi); resA.x = lo + hi; }
    { float lo, hi; unpack2(accA[1], lo, hi); resA.y = lo + hi; }
    { float lo, hi; unpack2(accA[2], lo, hi); resA.z = lo + hi; }
    { float lo, hi; unpack2(accA[3], lo, hi); resA.w = lo + hi; }
    reinterpret_cast<float4*>(g_rowterm)[((l*NB + b)*NN + x)*4 + q] = resA;

    float4 resB;
    { float lo, hi; unpack2(accB[0], lo, hi); resB.x = lo + hi + basev.x; }
    { float lo, hi; unpack2(accB[1], lo, hi); resB.y = lo + hi + basev.y; }
    { float lo, hi; unpack2(accB[2], lo, hi); resB.z = lo + hi + basev.z; }
    { float lo, hi; unpack2(accB[3], lo, hi); resB.w = lo + hi + basev.w; }
    reinterpret_cast<float4*>(out + (size_t)l*OW_STRIDE + OB_OFF)[(b*NN + x)*4 + q] = resB;
}

// ---------------- main output pass: 4 j-rows per block, cp.async 8-stage w ring ----------------
// grid (64, 16, 4), 256 threads. w streamed via cp.async.cg (prefetch distance 7);
// each thread reads ONLY its own 16B slot -> per-thread wait_group, no barrier in loop.
__global__ void __launch_bounds__(256, 2)
main_kernel(const float* __restrict__ w0, const float* __restrict__ w1,
            const float* __restrict__ w2, const float* __restrict__ w3,
            const float* __restrict__ b0, const float* __restrict__ b1,
            const float* __restrict__ b2, const float* __restrict__ b3,
            float* __restrict__ out){
    int l  = 3 - (int)blockIdx.z;
    int b  = 15 - (int)blockIdx.y;
    int jx = 63 - (int)blockIdx.x;
    int j0 = jx*4;
    int t = threadIdx.x;
    int q = t & 3;
    const float* w = (l==0)?w0:(l==1)?w1:(l==2)?w2:w3;

    const float4* wrow = reinterpret_cast<const float4*>(w) + (size_t)(b*NN + j0)*1024;
    const float4* rrow = reinterpret_cast<const float4*>(g_rowterm) + (size_t)(l*NB + b)*1024;
    float4*       orow = reinterpret_cast<float4*>(out + (size_t)l*OW_STRIDE) + (size_t)(b*NN + j0)*1024;

    __shared__ float4 wbuf[8][256];            // 32KB w ring
    __shared__ unsigned long long Tt_s[128];   // [d][c2] c-paired transposed T
    __shared__ float shcol[64];                // colterm rows j0..j0+3

    unsigned wb_base;
    asm("{ .reg .u64 tmp; cvta.to.shared.u64 tmp, %1; cvt.u32.u64 %0, tmp; }"
        : "=r"(wb_base) : "l"(wbuf));
    unsigned my_off = (unsigned)(t*16);

    // issue stages 0..6 (7 groups in flight)
    #pragma unroll
    for (int s=0; s<7; s++){
        CP_ASYNC16(wb_base + (unsigned)(s*4096) + my_off, wrow + s*256 + t);
        CP_COMMIT();
    }

    // rowterm (reused across all 4 j) — register resident
    float4 rv0 = __ldg(rrow + 0*256 + t);
    float4 rv1 = __ldg(rrow + 1*256 + t);
    float4 rv2 = __ldg(rrow + 2*256 + t);
    float4 rv3 = __ldg(rrow + 3*256 + t);

    if (t < 128){
        int d = t >> 3, c2 = t & 7;
        float lo = __ldg(&g_terms[(72+l)*256 + (2*c2  )*16 + d]);
        float hi = __ldg(&g_terms[(72+l)*256 + (2*c2+1)*16 + d]);
        Tt_s[t] = pack2(lo, hi);
    } else if (t >= 192){
        int r = t - 192;                // 0..63
        int jj = r >> 4, d = r & 15;
        int j = j0 + jj;
        float acc = __ldg(&g_basew[(l*NB + b)*NC + d]);
        const float* cs = &g_csums[((l*NB + b)*NN + j)*NC];
        const float* T1 = &g_terms[(68 + l)*256];          // t_w_wcol
        #pragma unroll
        for (int c=0; c<NC; c++) acc = fmaf(cs[c], T1[c*16 + d], acc);
        if (l > 0){
            const float* rs  = &g_rsums[(((l-1)*NB + b)*NN + j)*NC];
            const float* bp  = ((l-1)==0?b0:(l-1)==1?b1:(l-1)==2?b2:b3) + (b*NN + j)*NC;
            const float* Tm0 = &g_terms[(94 + (l-1))*256]; // t_w_wm1
            const float* Tm1 = &g_terms[(97 + (l-1))*256]; // t_w_bm1
            #pragma unroll
            for (int c=0; c<NC; c++){
                acc = fmaf(rs[c], Tm0[c*16 + d], acc);
                acc = fmaf(bp[c], Tm1[c*16 + d], acc);
            }
        }
        shcol[r] = acc;
    }
    __syncthreads();

    int q1 = q^1, q2 = q^2, q3 = q^3;
    ulonglong2 TT[4][4];
    #pragma unroll
    for (int dd=0; dd<4; dd++){
        const ulonglong2* row = reinterpret_cast<const ulonglong2*>(&Tt_s[(q*4+dd)*8]);
        TT[dd][0] = row[q];
        TT[dd][1] = row[q1];
        TT[dd][2] = row[q2];
        TT[dd][3] = row[q3];
    }

    #pragma unroll
    for (int u=0; u<16; u++){
        int kc = u & 3;
        int jj = u >> 2;

        if (u + 7 < 16){
            int s = u + 7;
            CP_ASYNC16(wb_base + (unsigned)((s & 7)*4096) + my_off, wrow + s*256 + t);
            CP_COMMIT();
        }
        // ensure stage u is complete (pending allowed = min(7, 15-u))
        if      (u < 9)  CP_WAIT(7);
        else if (u == 9)  CP_WAIT(6);
        else if (u == 10) CP_WAIT(5);
        else if (u == 11) CP_WAIT(4);
        else if (u == 12) CP_WAIT(3);
        else if (u == 13) CP_WAIT(2);
        else if (u == 14) CP_WAIT(1);
        else              CP_WAIT(0);

        float4 wv = wbuf[u & 7][t];

        unsigned long long a0 = pack2(wv.x, wv.y);
        unsigned long long a1 = pack2(wv.z, wv.w);
        unsigned long long c0 = __shfl_xor_sync(0xffffffffu, a0, 1);
        unsigned long long c1 = __shfl_xor_sync(0xffffffffu, a1, 1);
        unsigned long long e0 = __shfl_xor_sync(0xffffffffu, a0, 2);
        unsigned long long e1 = __shfl_xor_sync(0xffffffffu, a1, 2);
        unsigned long long f0 = __shfl_xor_sync(0xffffffffu, c0, 2);
        unsigned long long f1 = __shfl_xor_sync(0xffffffffu, c1, 2);

        unsigned long long acc[4] = {0ull, 0ull, 0ull, 0ull};
        #pragma unroll
        for (int dd=0; dd<4; dd++){
            fma2(acc[dd], a0, TT[dd][0].x);
            fma2(acc[dd], a1, TT[dd][0].y);
            fma2(acc[dd], c0, TT[dd][1].x);
            fma2(acc[dd], c1, TT[dd][1].y);
            fma2(acc[dd], e0, TT[dd][2].x);
            fma2(acc[dd], e1, TT[dd][2].y);
            fma2(acc[dd], f0, TT[dd][3].x);
            fma2(acc[dd], f1, TT[dd][3].y);
        }

        float4 colv = *reinterpret_cast<const float4*>(&shcol[jj*16 + q*4]);
        float4 rv = (kc==0) ? rv0 : (kc==1) ? rv1 : (kc==2) ? rv2 : rv3;
        float4 res;
        { float lo, hi; unpack2(acc[0], lo, hi); res.x = lo + hi; }
        { float lo, hi; unpack2(acc[1], lo, hi); res.y = lo + hi; }
        { float lo, hi; unpack2(acc[2], lo, hi); res.z = lo + hi; }
        { float lo, hi; unpack2(acc[3], lo, hi); res.w = lo + hi; }
        res.x += colv.x + rv.x;
        res.y += colv.y + rv.y;
        res.z += colv.z + rv.z;
        res.w += colv.w + rv.w;
        orow[u*256 + t] = res;
    }
}

// ---------------- launch ----------------
extern "C" void kernel_launch(void* const* d_in, const int* in_sizes, int n_in,
                              void* d_out, int out_size){
    (void)n_in; (void)out_size;
    const float* w[4]; const float* bb[4];
    int wi = 0, bi = 0;
    for (int i = 0; i < 8; i++){
        if (in_sizes[i] > 1000000) w[wi++] = (const float*)d_in[i];
        else                       bb[bi++] = (const float*)d_in[i];
    }
    const float* sw0 = (const float*)d_in[8];
    const float* sb0 = (const float*)d_in[9];
    const float* sw1 = (const float*)d_in[10];
    const float* sb1 = (const float*)d_in[11];
    const float* sw2 = (const float*)d_in[12];
    const float* sb2 = (const float*)d_in[13];
    const float* swo = (const float*)d_in[14];
    const float* sbo = (const float*)d_in[15];
    float* out = (float*)d_out;

    reduce_pass1<<<dim3(10, NB, NL), 256>>>(w[0], w[1], w[2], w[3],
                                            sw0, sb0, sw1, sb1, sw2, sb2, swo, sbo);
    reduce_pass2<<<64, 256>>>(bb[0], bb[1], bb[2], bb[3]);
    colrow_kernel<<<256, 256>>>(bb[0], bb[1], bb[2], bb[3], out);
    main_kernel<<<dim3(64, NB, NL), 256>>>(w[0], w[1], w[2], w[3],
                                           bb[0], bb[1], bb[2], bb[3], out);
}